// round 11
// baseline (speedup 1.0000x reference)
#include <cuda_runtime.h>
#include <cuda_bf16.h>
#include <cstdint>
#include <cstddef>

#define HID 128
#define GSZ 512
#define BATCH 1024
#define TLEN 512
#define DIN 12
#define BT 8
#define NBLK 128
#define MROWS (TLEN*BATCH)
#define AS 264
#define BSTR 392
#define ASTR 136     // A_s bf16 row stride
#define BUFS 516     // gate/xp buffer fp32 row stride

typedef unsigned long long ull;

// ---------------- device globals ----------------
__device__ ull g_Wpk[2][32768];                      // packed W_hh frag planes (hi|lo)
__device__ float g_bias1[GSZ];
__device__ __nv_bfloat16 g_h1s[(size_t)MROWS*256];   // h1 [row][hi128|lo128]
__device__ __nv_bfloat16 g_BE[GSZ*384];              // W_ih1 ext [n][384]=wh|wh|wl
__device__ float g_xp0[(size_t)MROWS*GSZ];           // x@Wih0^T + b0  [t][b][512]
__device__ float g_xp1[(size_t)MROWS*GSZ];           // h1@Wih1^T + b1 [t][b][512]
__device__ float g_h2[BATCH*HID];

// ---------------- helpers ----------------
__device__ __forceinline__ float sigm(float x){return __fdividef(1.0f,1.0f+__expf(-x));}
__device__ __forceinline__ float tanh_f(float x){return __fdividef(2.0f,1.0f+__expf(-2.0f*x))-1.0f;}
__device__ __forceinline__ uint32_t pkbf(float a, float b){
    __nv_bfloat16 ha=__float2bfloat16(a), hb=__float2bfloat16(b);
    return (uint32_t)__bfloat16_as_ushort(ha) | ((uint32_t)__bfloat16_as_ushort(hb)<<16);
}
#define MMA(d,a,b0,b1) \
    asm volatile("mma.sync.aligned.m16n8k16.row.col.f32.bf16.bf16.f32 " \
        "{%0,%1,%2,%3},{%4,%5,%6,%7},{%8,%9},{%0,%1,%2,%3};" \
        : "+f"((d)[0]),"+f"((d)[1]),"+f"((d)[2]),"+f"((d)[3]) \
        : "r"((a)[0]),"r"((a)[1]),"r"((a)[2]),"r"((a)[3]),"r"(b0),"r"(b1))

// ---------------- prep: pack W_hh frag planes + W_ih1 ext + bias1 ----------------
__global__ void prep_kernel(const float* __restrict__ Whh0, const float* __restrict__ Whh1,
                            const float* __restrict__ Wih1,
                            const float* __restrict__ bih1, const float* __restrict__ bhh1){
    int i = blockIdx.x*blockDim.x + threadIdx.x;
    if(i < 65536){
        int L = i>>15, u = i&32767;
        int lane=u&31, ni=(u>>5)&7, c=(u>>8)&7, p=(u>>11)&1, w=(u>>12)&7;
        int g=lane>>2, tq=lane&3;
        int n = w*64 + ni*8 + g;
        int k0 = c*16 + 2*tq;
        const float* W = L ? Whh1 : Whh0;
        float v[4];
#pragma unroll
        for(int e=0;e<4;e++){
            int k = k0 + (e>>1)*8 + (e&1);
            float x = W[n*HID + k];
            __nv_bfloat16 hi = __float2bfloat16(x);
            v[e] = p==0 ? __bfloat162float(hi) : (x - __bfloat162float(hi));
        }
        uint32_t b0 = pkbf(v[0], v[1]);
        uint32_t b1 = pkbf(v[2], v[3]);
        g_Wpk[L][u] = (ull)b0 | ((ull)b1<<32);
    } else if(i < 65536 + GSZ*384){
        int i2 = i - 65536;
        int n=i2/384, kp=i2%384, k=kp&127;
        float w = Wih1[n*HID+k];
        __nv_bfloat16 hi = __float2bfloat16(w);
        g_BE[i2] = (kp<256) ? hi : __float2bfloat16(w - __bfloat162float(hi));
    } else if(i < 65536 + GSZ*384 + GSZ){
        int j = i - 65536 - GSZ*384;
        g_bias1[j] = bih1[j] + bhh1[j];
    }
}

// ---------------- xp0 = x @ Wih0^T + (bih0+bhh0), layout [t][b][512] ----------------
__global__ void __launch_bounds__(256,1) xp0_kernel(const float* __restrict__ x,
        const float* __restrict__ Wih0, const float* __restrict__ bih0,
        const float* __restrict__ bhh0){
    __shared__ float Ws[GSZ*DIN];
    __shared__ float bs[GSZ];
    __shared__ float xs[16*DIN];
    int t = blockIdx.x, bb = blockIdx.y*16, tid = threadIdx.x;
    for(int i=tid;i<GSZ*DIN;i+=256) Ws[i]=Wih0[i];
    for(int i=tid;i<GSZ;i+=256) bs[i]=bih0[i]+bhh0[i];
    if(tid<192){ int r=tid/DIN, d=tid%DIN;
        xs[tid] = x[((size_t)(bb+r)*TLEN + t)*DIN + d]; }
    __syncthreads();
    int r = tid>>4, cl = tid&15;
    const float* xr = &xs[r*DIN];
    float* outp = &g_xp0[(((size_t)t)*BATCH + bb + r)*GSZ];
#pragma unroll 4
    for(int j=0;j<32;j++){
        int col = cl + j*16;
        const float* wj = &Ws[col*DIN];
        float s = bs[col];
#pragma unroll
        for(int d=0;d<DIN;d++) s += xr[d]*wj[d];
        outp[col] = s;
    }
}

// ---------------- xp1 = h1(split bf16) @ Wih1^T + b1 (mma.sync, smem A+B) ----------
__global__ void __launch_bounds__(256,1) xp_gemm_kernel(){
    extern __shared__ __nv_bfloat16 sh[];
    __nv_bfloat16* As = sh;
    __nv_bfloat16* Bs = sh + 128*AS;
    int tid=threadIdx.x, wid=tid>>5, lane=tid&31;
    int g=lane>>2, tq=lane&3;
    size_t mbase=(size_t)blockIdx.x*128;
    int ny=blockIdx.y;
    {
        const float4* src=(const float4*)(g_h1s + mbase*256);
        for(int i=tid;i<4096;i+=256){
            int r=i>>5, c=i&31;
            *(float4*)(As + r*AS + c*8)=src[r*32+c];
        }
        const float4* bsrc=(const float4*)(g_BE + (size_t)ny*128*384);
        for(int i=tid;i<6144;i+=256){
            int n=i/48, kq=i%48;
            *(float4*)(Bs + n*BSTR + kq*8)=bsrc[i];
        }
    }
    __syncthreads();
    int nl0=(wid>>2)*64;
    int m0=(wid&3)*32;
    float acc[2][8][4];
#pragma unroll
    for(int mi=0;mi<2;mi++)
#pragma unroll
        for(int ni=0;ni<8;ni++)
#pragma unroll
            for(int q=0;q<4;q++) acc[mi][ni][q]=0.f;
#pragma unroll 1
    for(int kc=0;kc<24;kc++){
        int ks=(kc<8)?kc*16:(kc<16)?(128+(kc-8)*16):((kc-16)*16);
        int kb=kc*16;
        uint32_t a[2][4];
#pragma unroll
        for(int mi=0;mi<2;mi++){
            const __nv_bfloat16* ap=As+(m0+mi*16)*AS+ks;
            a[mi][0]=*(const uint32_t*)(ap+g*AS+2*tq);
            a[mi][1]=*(const uint32_t*)(ap+(g+8)*AS+2*tq);
            a[mi][2]=*(const uint32_t*)(ap+g*AS+2*tq+8);
            a[mi][3]=*(const uint32_t*)(ap+(g+8)*AS+2*tq+8);
        }
#pragma unroll
        for(int ni=0;ni<8;ni++){
            const __nv_bfloat16* bp=Bs+(nl0+ni*8+g)*BSTR+kb;
            uint32_t b0=*(const uint32_t*)(bp+2*tq);
            uint32_t b1=*(const uint32_t*)(bp+2*tq+8);
            MMA(acc[0][ni],a[0],b0,b1);
            MMA(acc[1][ni],a[1],b0,b1);
        }
    }
#pragma unroll
    for(int mi=0;mi<2;mi++)
#pragma unroll
        for(int ni=0;ni<8;ni++){
            int col=ny*128+nl0+ni*8+2*tq;
            float bx=g_bias1[col], by=g_bias1[col+1];
            size_t r0=mbase+m0+mi*16+g;
            *(float2*)&g_xp1[r0*GSZ+col]     = make_float2(acc[mi][ni][0]+bx, acc[mi][ni][1]+by);
            *(float2*)&g_xp1[(r0+8)*GSZ+col] = make_float2(acc[mi][ni][2]+bx, acc[mi][ni][3]+by);
        }
}

// ---------------- tensor-core LSTM scan ----------------
// 128 blocks x 256 threads; BT=8 batch rows. A = [h_hi(8); h_lo(8)] packed M=16.
// Each k-chunk runs vs W_hi and W_lo planes: D(g)+D(g+8) = exact split-2x2 product.
// gates buf (fp32) doubles as xp staging (read xp, add acc, write gates in place).
template <int LAYER>
__global__ void __launch_bounds__(256,1) lstm_scan(){
    extern __shared__ char smem[];
    ull*  ws  = (ull*)smem;                               // 8 warps x 3072 ull = 196,608B
    __nv_bfloat16* A_s = (__nv_bfloat16*)(smem + 196608); // [16][ASTR] = 4,352B
    float* buf = (float*)(smem + 196608 + 4352);          // [8][BUFS]  = 16,512B

    const float* __restrict__ xp = LAYER ? g_xp1 : g_xp0;
    const int tid = threadIdx.x;
    const int w = tid>>5, lane = tid&31, g = lane>>2, tq = lane&3;
    const int b0 = blockIdx.x*BT;

    // copy W frags into smem: hi chunks 0-7 (slots 0-7), lo chunks 0-3 (slots 8-11)
    for(int i=lane;i<3072;i+=32){
        int s=i>>8, rem=i&255;
        ws[w*3072+i] = g_Wpk[LAYER][w*4096 + (s<8 ? s*256 : 2048+(s-8)*256) + rem];
    }
    // lo chunks 4-7 -> persistent registers
    uint2 wreg[4][8];
#pragma unroll
    for(int cc=0;cc<4;cc++)
#pragma unroll
        for(int ni=0;ni<8;ni++){
            ull v = g_Wpk[LAYER][w*4096 + 2048 + (4+cc)*256 + ni*32 + lane];
            wreg[cc][ni] = make_uint2((uint32_t)v,(uint32_t)(v>>32));
        }
    for(int i=tid;i<16*ASTR/2;i+=256) ((uint32_t*)A_s)[i]=0;   // h0 = 0

    const int ur = tid>>5, um = (tid&31)*4;     // update: row, 4 hidden cells
    float c_r[4]={0.f,0.f,0.f,0.f};

#pragma unroll 1
    for(int t=0;t<TLEN;t++){
        // stage xp[t] for this block's 8 rows (4 float4/thread, coalesced)
        float4 xs[4];
#pragma unroll
        for(int i=0;i<4;i++){
            int fi = tid + i*256;
            xs[i] = *(const float4*)&xp[(((size_t)t)*BATCH + b0 + (fi>>7))*GSZ + (fi&127)*4];
        }
        // update phase: consume gates(t-1) from buf
        if(t>0){
            float4 gi=*(float4*)&buf[ur*BUFS+um];
            float4 gf=*(float4*)&buf[ur*BUFS+128+um];
            float4 gg=*(float4*)&buf[ur*BUFS+256+um];
            float4 go=*(float4*)&buf[ur*BUFS+384+um];
            float hv[4], lv[4];
#pragma unroll
            for(int e=0;e<4;e++){
                float iv=sigm(((float*)&gi)[e]);
                float fv=sigm(((float*)&gf)[e]);
                float gv=tanh_f(((float*)&gg)[e]);
                float ov=sigm(((float*)&go)[e]);
                float c=fv*c_r[e]+iv*gv; c_r[e]=c;
                float h=ov*tanh_f(c);
                __nv_bfloat16 hb=__float2bfloat16(h);
                hv[e]=__bfloat162float(hb);
                lv[e]=h-hv[e];
            }
            uint2 ph=make_uint2(pkbf(hv[0],hv[1]),pkbf(hv[2],hv[3]));
            uint2 pl=make_uint2(pkbf(lv[0],lv[1]),pkbf(lv[2],lv[3]));
            *(uint2*)&A_s[ur*ASTR+um]     = ph;     // hi rows 0-7
            *(uint2*)&A_s[(ur+8)*ASTR+um] = pl;     // lo rows 8-15
            if(LAYER==0){
                size_t row=((size_t)(t-1))*BATCH+b0+ur;
                *(uint2*)&g_h1s[row*256+um]     = ph;
                *(uint2*)&g_h1s[row*256+128+um] = pl;
            }
        }
        // commit xp into buf
#pragma unroll
        for(int i=0;i<4;i++){
            int fi = tid + i*256;
            *(float4*)&buf[(fi>>7)*BUFS + (fi&127)*4] = xs[i];
        }
        __syncthreads();

        // MMA: gates_rec, split-exact
        float acc[8][4];
#pragma unroll
        for(int ni=0;ni<8;ni++){acc[ni][0]=0;acc[ni][1]=0;acc[ni][2]=0;acc[ni][3]=0;}
#pragma unroll
        for(int c=0;c<8;c++){
            uint32_t a[4];
            a[0]=*(const uint32_t*)&A_s[g*ASTR + 16*c + 2*tq];
            a[1]=*(const uint32_t*)&A_s[(g+8)*ASTR + 16*c + 2*tq];
            a[2]=*(const uint32_t*)&A_s[g*ASTR + 16*c + 2*tq + 8];
            a[3]=*(const uint32_t*)&A_s[(g+8)*ASTR + 16*c + 2*tq + 8];
            const uint2* whc = (const uint2*)&ws[w*3072 + c*256] + lane;
#pragma unroll
            for(int ni=0;ni<8;ni++){
                uint2 bh = whc[ni*32];
                MMA(acc[ni],a,bh.x,bh.y);
            }
            if(c<4){
                const uint2* wlc = (const uint2*)&ws[w*3072 + (8+c)*256] + lane;
#pragma unroll
                for(int ni=0;ni<8;ni++){
                    uint2 bl = wlc[ni*32];
                    MMA(acc[ni],a,bl.x,bl.y);
                }
            } else {
#pragma unroll
                for(int ni=0;ni<8;ni++)
                    MMA(acc[ni],a,wreg[c-4][ni].x,wreg[c-4][ni].y);
            }
        }
        // epilogue: gate = xp + D(hi row) + D(lo row); rows combine in-thread
#pragma unroll
        for(int ni=0;ni<8;ni++){
            int c0 = w*64 + ni*8 + 2*tq;
            float2 v = *(float2*)&buf[g*BUFS + c0];
            v.x += acc[ni][0] + acc[ni][2];
            v.y += acc[ni][1] + acc[ni][3];
            *(float2*)&buf[g*BUFS + c0] = v;
        }
        __syncthreads();
    }
    // final update (t = T-1)
    {
        float4 gi=*(float4*)&buf[ur*BUFS+um];
        float4 gf=*(float4*)&buf[ur*BUFS+128+um];
        float4 gg=*(float4*)&buf[ur*BUFS+256+um];
        float4 go=*(float4*)&buf[ur*BUFS+384+um];
        float hv[4], lv[4];
#pragma unroll
        for(int e=0;e<4;e++){
            float iv=sigm(((float*)&gi)[e]);
            float fv=sigm(((float*)&gf)[e]);
            float gv=tanh_f(((float*)&gg)[e]);
            float ov=sigm(((float*)&go)[e]);
            float c=fv*c_r[e]+iv*gv;
            float h=ov*tanh_f(c);
            __nv_bfloat16 hb=__float2bfloat16(h);
            hv[e]=__bfloat162float(hb);
            lv[e]=h-hv[e];
            if(LAYER==1) g_h2[(b0+ur)*HID+um+e]=h;
        }
        if(LAYER==0){
            size_t row=((size_t)(TLEN-1))*BATCH+b0+ur;
            *(uint2*)&g_h1s[row*256+um]     = make_uint2(pkbf(hv[0],hv[1]),pkbf(hv[2],hv[3]));
            *(uint2*)&g_h1s[row*256+128+um] = make_uint2(pkbf(lv[0],lv[1]),pkbf(lv[2],lv[3]));
        }
    }
}

// ---------------- MLP head ----------------
__global__ void head_kernel(const float* __restrict__ W1,const float* __restrict__ b1,
                            const float* __restrict__ W2,const float* __restrict__ b2,
                            const float* __restrict__ W3,const float* __restrict__ b3,
                            float* __restrict__ out){
    __shared__ float hrow[HID]; __shared__ float z1[64]; __shared__ float z2[32];
    int b=blockIdx.x, tid=threadIdx.x;
    hrow[tid]=g_h2[b*HID+tid];
    hrow[tid+64]=g_h2[b*HID+tid+64];
    __syncthreads();
    {
        float s=b1[tid];
        const float* wp=&W1[tid*HID];
#pragma unroll 8
        for(int k=0;k<HID;k++) s+=wp[k]*hrow[k];
        z1[tid]=fmaxf(s,0.f);
    }
    __syncthreads();
    if(tid<32){
        float s=b2[tid];
        const float* wp=&W2[tid*64];
#pragma unroll 8
        for(int k=0;k<64;k++) s+=wp[k]*z1[k];
        z2[tid]=fmaxf(s,0.f);
    }
    __syncthreads();
    if(tid<2){
        float s=b3[tid];
        const float* wp=&W3[tid*32];
#pragma unroll
        for(int k=0;k<32;k++) s+=wp[k]*z2[k];
        out[b*2+tid]=s;
    }
}

// ---------------- launch ----------------
extern "C" void kernel_launch(void* const* d_in, const int* in_sizes, int n_in,
                              void* d_out, int out_size){
    const float* x   =(const float*)d_in[0];
    const float* Wih0=(const float*)d_in[1];
    const float* Whh0=(const float*)d_in[2];
    const float* bih0=(const float*)d_in[3];
    const float* bhh0=(const float*)d_in[4];
    const float* Wih1=(const float*)d_in[5];
    const float* Whh1=(const float*)d_in[6];
    const float* bih1=(const float*)d_in[7];
    const float* bhh1=(const float*)d_in[8];
    const float* W1=(const float*)d_in[9];
    const float* b1=(const float*)d_in[10];
    const float* W2=(const float*)d_in[11];
    const float* b2=(const float*)d_in[12];
    const float* W3=(const float*)d_in[13];
    const float* b3=(const float*)d_in[14];
    float* out=(float*)d_out;

    const int smems = 196608 + 4352 + 16512;      // 217,472 B
    const int smemg = (128*AS + 128*BSTR)*2;      // 167,936 B
    cudaFuncSetAttribute((const void*)lstm_scan<0>,cudaFuncAttributeMaxDynamicSharedMemorySize,smems);
    cudaFuncSetAttribute((const void*)lstm_scan<1>,cudaFuncAttributeMaxDynamicSharedMemorySize,smems);
    cudaFuncSetAttribute((const void*)xp_gemm_kernel,cudaFuncAttributeMaxDynamicSharedMemorySize,smemg);

    int tot = 65536 + GSZ*384 + GSZ;
    prep_kernel<<<(tot+255)/256,256>>>(Whh0,Whh1,Wih1,bih1,bhh1);
    xp0_kernel<<<dim3(TLEN,BATCH/16),256>>>(x,Wih0,bih0,bhh0);
    lstm_scan<0><<<NBLK,256,smems>>>();
    xp_gemm_kernel<<<dim3(MROWS/128,4),256,smemg>>>();
    lstm_scan<1><<<NBLK,256,smems>>>();
    head_kernel<<<BATCH,64>>>(W1,b1,W2,b2,W3,b3,out);
}

// round 13
// speedup vs baseline: 1.2493x; 1.2493x over previous
#include <cuda_runtime.h>
#include <cuda_bf16.h>
#include <cstdint>
#include <cstddef>

#define HID 128
#define GSZ 512
#define BATCH 1024
#define TLEN 512
#define DIN 12
#define KP0 144
#define KP1 128
#define SRR 96
#define BT 8
#define NBLK 128
#define MROWS (TLEN*BATCH)
#define AS2 264      // A smem stride (bf16) — 264*4%32=1 bank offset/row group
#define BS2 392      // B smem stride (bf16)
#define NTILE 64     // 64-row A tiles per CTA

typedef unsigned long long ull;

// ---------------- device globals ----------------
__device__ float g_W0T[KP0*GSZ];                     // [k][j] L0 weights (x|h concat)
__device__ float g_W1T[KP1*GSZ];                     // [k][j] L1 W_hh only
__device__ float g_bias0[GSZ];
__device__ float g_bias1[GSZ];
__device__ __nv_bfloat16 g_h1s[(size_t)MROWS*256];   // h1 [row][hi128|lo128]
__device__ __nv_bfloat16 g_BE[GSZ*384];              // W_ih1 ext [n][384] = wh|wh|wl
__device__ float g_xp1[(size_t)MROWS*GSZ];           // h1@Wih1^T + b1, [t][b][512]
__device__ float g_h2[BATCH*HID];

// ---------------- helpers ----------------
__device__ __forceinline__ ull dup2(float x){ull d;asm("mov.b64 %0,{%1,%1};":"=l"(d):"f"(x));return d;}
__device__ __forceinline__ ull pk2(float x,float y){ull d;asm("mov.b64 %0,{%1,%2};":"=l"(d):"f"(x),"f"(y));return d;}
__device__ __forceinline__ ull fma2(ull a,ull b,ull c){ull d;asm("fma.rn.f32x2 %0,%1,%2,%3;":"=l"(d):"l"(a),"l"(b),"l"(c));return d;}
__device__ __forceinline__ float2 unp(ull v){float2 r;asm("mov.b64 {%0,%1},%2;":"=f"(r.x),"=f"(r.y):"l"(v));return r;}
__device__ __forceinline__ float sigm(float x){return __fdividef(1.0f,1.0f+__expf(-x));}
__device__ __forceinline__ float tanh_f(float x){return __fdividef(2.0f,1.0f+__expf(-2.0f*x))-1.0f;}
__device__ __forceinline__ uint32_t smem_u32(const void* p){
    uint32_t a;
    asm("{ .reg .u64 t; cvta.to.shared.u64 t, %1; cvt.u32.u64 %0, t; }":"=r"(a):"l"(p));
    return a;
}

#define MMA(d,a,b0,b1) \
    asm volatile("mma.sync.aligned.m16n8k16.row.col.f32.bf16.bf16.f32 " \
        "{%0,%1,%2,%3},{%4,%5,%6,%7},{%8,%9},{%0,%1,%2,%3};" \
        : "+f"((d)[0]),"+f"((d)[1]),"+f"((d)[2]),"+f"((d)[3]) \
        : "r"((a)[0]),"r"((a)[1]),"r"((a)[2]),"r"((a)[3]),"r"(b0),"r"(b1))

#define CP16(dst,src) \
    asm volatile("cp.async.cg.shared.global [%0], [%1], 16;"::"r"(dst),"l"(src))
#define CP_COMMIT() asm volatile("cp.async.commit_group;" ::: "memory")
#define CP_WAIT0()  asm volatile("cp.async.wait_group 0;" ::: "memory")

// one weight row (2 gate cols) x 8 batch rows -> 8 f32x2 accumulators
#define FMA_ROW(W2V,KIDX) do{ \
    ull w0=dup2((W2V).x), w1=dup2((W2V).y); \
    ulonglong2 vA=*(const ulonglong2*)&v_s[(KIDX)*12]; \
    ulonglong2 vB=*(const ulonglong2*)&v_s[(KIDX)*12+4]; \
    a0=fma2(w0,vA.x,a0); a1=fma2(w0,vA.y,a1); \
    a2=fma2(w0,vB.x,a2); a3=fma2(w0,vB.y,a3); \
    a4=fma2(w1,vA.x,a4); a5=fma2(w1,vA.y,a5); \
    a6=fma2(w1,vB.x,a6); a7=fma2(w1,vB.y,a7); }while(0)

// ---------------- prep ----------------
__global__ void prep_kernel(const float* __restrict__ Wih0,const float* __restrict__ Whh0,
                            const float* __restrict__ bih0,const float* __restrict__ bhh0,
                            const float* __restrict__ Wih1,const float* __restrict__ Whh1,
                            const float* __restrict__ bih1,const float* __restrict__ bhh1){
    int i = blockIdx.x*blockDim.x + threadIdx.x;
    const int S0=KP0*GSZ, S1=S0+KP1*GSZ, S2=S1+GSZ, S3=S2+GSZ, S4=S3+GSZ*384;
    if(i<S0){
        int k=i/GSZ, j=i%GSZ; float v=0.f;
        if(k<DIN) v=Wih0[j*DIN+k]; else if(k<DIN+HID) v=Whh0[j*HID+(k-DIN)];
        g_W0T[i]=v;
    }else if(i<S1){
        int i2=i-S0; int k=i2/GSZ, j=i2%GSZ;
        g_W1T[i2]=Whh1[j*HID+k];
    }else if(i<S2){ int j=i-S1; g_bias0[j]=bih0[j]+bhh0[j]; }
    else if(i<S3){ int j=i-S2; g_bias1[j]=bih1[j]+bhh1[j]; }
    else if(i<S4){
        int i2=i-S3; int n=i2/384, kp=i2%384, k=kp&127;
        float w=Wih1[n*HID+k];
        __nv_bfloat16 hi=__float2bfloat16(w);
        g_BE[i2] = (kp<256)? hi : __float2bfloat16(w-__bfloat162float(hi));
    }
}

// prefetch one 64-row A tile (64 x 256 bf16 = 32KB) via cp.async
__device__ __forceinline__ void prefetchA(size_t mt, __nv_bfloat16* buf, int tid){
    const char* src = (const char*)(g_h1s + mt*64*256);
    uint32_t dbase = smem_u32(buf);
#pragma unroll
    for(int c=0;c<8;c++){
        int chunk = tid + c*256;            // 2048 x 16B chunks
        int r = chunk>>5, col16 = chunk&31;
        uint32_t d = dbase + (uint32_t)(r*AS2*2 + col16*16);
        CP16(d, src + r*512 + col16*16);
    }
    CP_COMMIT();
}

// ---------------- xp1 GEMM: pipelined mma.sync ----------------
// Grid (128 msets, 4 ny). Per CTA: B tile (128n x 384k) resident in smem;
// 64 A tiles (64 rows each) double-buffered via cp.async.
// Split-3 exact: A_ext cols hi|lo|hi vs B_ext wh|wh|wl.
__global__ void __launch_bounds__(256,1) xp_tc2_kernel(){
    extern __shared__ __nv_bfloat16 sh[];
    __nv_bfloat16* Bs = sh;                  // [128][BS2] = 100,352B
    __nv_bfloat16* A0 = sh + 128*BS2;        // [64][AS2]  =  33,792B
    __nv_bfloat16* A1 = A0 + 64*AS2;         //            =  33,792B
    const int tid=threadIdx.x, wid=tid>>5, lane=tid&31;
    const int g=lane>>2, tq=lane&3;
    const int mset=blockIdx.x, ny=blockIdx.y;

    // B tile once
    {
        const float4* bsrc=(const float4*)(g_BE + (size_t)ny*128*384);
        for(int i=tid;i<6144;i+=256){
            int n=i/48, kq=i%48;
            *(float4*)(Bs + n*BS2 + kq*8)=bsrc[i];
        }
    }
    const int n0=(wid>>2)*64;       // n-half within 128
    const int m0=(wid&3)*16;        // m-quarter within 64

    float bx[8], by[8];
#pragma unroll
    for(int ni=0;ni<8;ni++){
        int col=ny*128+n0+ni*8+2*tq;
        bx[ni]=g_bias1[col]; by[ni]=g_bias1[col+1];
    }

    prefetchA((size_t)mset, A0, tid);
    __syncthreads();    // B visible

#pragma unroll 1
    for(int i=0;i<NTILE;i++){
        __nv_bfloat16* Ac = (i&1)? A1 : A0;
        CP_WAIT0();
        __syncthreads();                        // A tile i visible to all
        if(i+1<NTILE)
            prefetchA((size_t)mset + 128*(size_t)(i+1), (i&1)? A0 : A1, tid);

        float acc[8][4];
#pragma unroll
        for(int ni=0;ni<8;ni++){acc[ni][0]=0;acc[ni][1]=0;acc[ni][2]=0;acc[ni][3]=0;}
#pragma unroll 2
        for(int kc=0;kc<24;kc++){
            int ks=(kc<8)?kc*16:(kc<16)?(128+(kc-8)*16):((kc-16)*16);
            int kb=kc*16;
            uint32_t a[4];
            const __nv_bfloat16* ap=Ac+m0*AS2+ks;
            a[0]=*(const uint32_t*)(ap+g*AS2+2*tq);
            a[1]=*(const uint32_t*)(ap+(g+8)*AS2+2*tq);
            a[2]=*(const uint32_t*)(ap+g*AS2+2*tq+8);
            a[3]=*(const uint32_t*)(ap+(g+8)*AS2+2*tq+8);
#pragma unroll
            for(int ni=0;ni<8;ni++){
                const __nv_bfloat16* bp=Bs+(n0+ni*8+g)*BS2+kb;
                uint32_t b0=*(const uint32_t*)(bp+2*tq);
                uint32_t b1=*(const uint32_t*)(bp+2*tq+8);
                MMA(acc[ni],a,b0,b1);
            }
        }
        // epilogue
        {
            size_t r0=((size_t)mset + 128*(size_t)i)*64 + m0 + g;
            int colb=ny*128+n0;
#pragma unroll
            for(int ni=0;ni<8;ni++){
                int col=colb+ni*8+2*tq;
                *(float2*)&g_xp1[r0*GSZ+col]     = make_float2(acc[ni][0]+bx[ni], acc[ni][1]+by[ni]);
                *(float2*)&g_xp1[(r0+8)*GSZ+col] = make_float2(acc[ni][2]+bx[ni], acc[ni][3]+by[ni]);
            }
        }
        __syncthreads();   // all warps done with Ac before it is overwritten
    }
}

// ---------------- fused LSTM scan (R8-exact) ----------------
template <int LAYER>
__global__ void __launch_bounds__(256,1) lstm_kernel(const float* __restrict__ x){
    constexpr int KP=(LAYER==0)?KP0:KP1;
    constexpr int PRM=KP-SRR;                 // 48 / 32
    constexpr int KOFF=(LAYER==0)?DIN:0;
    const float* __restrict__ WT=(LAYER==0)?g_W0T:g_W1T;

    extern __shared__ float smem[];
    float* w_s=smem;                 // SRR*512
    float* v_s=w_s+SRR*GSZ;          // KP*12
    float* g_s=v_s+KP*12;            // 8*512

    const int tid=threadIdx.x;
    const int b0=blockIdx.x*BT;
    const int j0=2*tid;
    {
        const float2* src=(const float2*)WT;
        float2* dst=(float2*)w_s;
        for(int i=tid;i<SRR*GSZ/2;i+=256) dst[i]=src[i];
    }
    for(int i=tid;i<KP*12;i+=256) v_s[i]=0.f;

    float2 pbuf[PRM];
#pragma unroll
    for(int i=0;i<PRM;i++) pbuf[i]=*(const float2*)&WT[(SRR+i)*GSZ+j0];

    ull bxd=0, byd=0;
    if(LAYER==0){
        float2 bj=*(const float2*)&g_bias0[j0];
        bxd=dup2(bj.x); byd=dup2(bj.y);
    }
    const int ub=tid>>5, um=tid&31;
    float c_r[4]={0.f,0.f,0.f,0.f};

    for(int t=0;t<TLEN;t++){
        float xstage=0.f; float2 xpr[8];
        int st_r=0, st_d=0;
        if(LAYER==0){
            if(tid<96){ st_r=tid/12; st_d=tid%12;
                xstage=x[(((size_t)(b0+st_r))*TLEN+t)*DIN+st_d]; }
        }else{
            const float* xpb=g_xp1+(((size_t)t)*BATCH+b0)*GSZ+j0;
#pragma unroll
            for(int b=0;b<8;b++) xpr[b]=*(const float2*)(xpb+(size_t)b*GSZ);
        }
        if(t>0){
#pragma unroll
            for(int q=0;q<4;q++){
                int m=um+32*q;
                float iv=sigm(g_s[ub*GSZ+m]);
                float fv=sigm(g_s[ub*GSZ+128+m]);
                float gv=tanh_f(g_s[ub*GSZ+256+m]);
                float ov=sigm(g_s[ub*GSZ+384+m]);
                float c=fv*c_r[q]+iv*gv; c_r[q]=c;
                float h=ov*tanh_f(c);
                v_s[(KOFF+m)*12+ub]=h;
                if(LAYER==0){
                    size_t row=((size_t)(t-1))*BATCH+b0+ub;
                    __nv_bfloat16 hb=__float2bfloat16(h);
                    g_h1s[row*256+m]=hb;
                    g_h1s[row*256+128+m]=__float2bfloat16(h-__bfloat162float(hb));
                }
            }
        }
        if(LAYER==0){ if(tid<96) v_s[st_d*12+st_r]=xstage; }
        __syncthreads();

        ull a0,a1,a2,a3,a4,a5,a6,a7;
        if(LAYER==0){ a0=bxd;a1=bxd;a2=bxd;a3=bxd; a4=byd;a5=byd;a6=byd;a7=byd; }
        else{
            a0=pk2(xpr[0].x,xpr[1].x); a1=pk2(xpr[2].x,xpr[3].x);
            a2=pk2(xpr[4].x,xpr[5].x); a3=pk2(xpr[6].x,xpr[7].x);
            a4=pk2(xpr[0].y,xpr[1].y); a5=pk2(xpr[2].y,xpr[3].y);
            a6=pk2(xpr[4].y,xpr[5].y); a7=pk2(xpr[6].y,xpr[7].y);
        }
#pragma unroll 4
        for(int k=0;k<SRR;k++){
            float2 w=*(const float2*)&w_s[k*GSZ+j0];
            FMA_ROW(w,k);
        }
#pragma unroll
        for(int i=0;i<PRM;i++) FMA_ROW(pbuf[i],SRR+i);
        {
            ull ac0[4]={a0,a1,a2,a3}, ac1[4]={a4,a5,a6,a7};
#pragma unroll
            for(int p=0;p<4;p++){
                float2 u0=unp(ac0[p]), u1=unp(ac1[p]);
                *(float2*)&g_s[(2*p)*GSZ+j0]  =make_float2(u0.x,u1.x);
                *(float2*)&g_s[(2*p+1)*GSZ+j0]=make_float2(u0.y,u1.y);
            }
        }
        __syncthreads();
    }
#pragma unroll
    for(int q=0;q<4;q++){
        int m=um+32*q;
        float iv=sigm(g_s[ub*GSZ+m]);
        float fv=sigm(g_s[ub*GSZ+128+m]);
        float gv=tanh_f(g_s[ub*GSZ+256+m]);
        float ov=sigm(g_s[ub*GSZ+384+m]);
        float c=fv*c_r[q]+iv*gv;
        float h=ov*tanh_f(c);
        if(LAYER==0){
            size_t row=((size_t)(TLEN-1))*BATCH+b0+ub;
            __nv_bfloat16 hb=__float2bfloat16(h);
            g_h1s[row*256+m]=hb;
            g_h1s[row*256+128+m]=__float2bfloat16(h-__bfloat162float(hb));
        }else g_h2[(b0+ub)*HID+m]=h;
    }
}

// ---------------- MLP head ----------------
__global__ void head_kernel(const float* __restrict__ W1,const float* __restrict__ b1,
                            const float* __restrict__ W2,const float* __restrict__ b2,
                            const float* __restrict__ W3,const float* __restrict__ b3,
                            float* __restrict__ out){
    __shared__ float hrow[HID]; __shared__ float z1[64]; __shared__ float z2[32];
    int b=blockIdx.x, tid=threadIdx.x;
    hrow[tid]=g_h2[b*HID+tid];
    hrow[tid+64]=g_h2[b*HID+tid+64];
    __syncthreads();
    {
        float s=b1[tid];
        const float* w=&W1[tid*HID];
#pragma unroll 8
        for(int k=0;k<HID;k++) s+=w[k]*hrow[k];
        z1[tid]=fmaxf(s,0.f);
    }
    __syncthreads();
    if(tid<32){
        float s=b2[tid];
        const float* w=&W2[tid*64];
#pragma unroll 8
        for(int k=0;k<64;k++) s+=w[k]*z1[k];
        z2[tid]=fmaxf(s,0.f);
    }
    __syncthreads();
    if(tid<2){
        float s=b3[tid];
        const float* w=&W3[tid*32];
#pragma unroll
        for(int k=0;k<32;k++) s+=w[k]*z2[k];
        out[b*2+tid]=s;
    }
}

// ---------------- launch ----------------
extern "C" void kernel_launch(void* const* d_in, const int* in_sizes, int n_in,
                              void* d_out, int out_size){
    const float* x   =(const float*)d_in[0];
    const float* Wih0=(const float*)d_in[1];
    const float* Whh0=(const float*)d_in[2];
    const float* bih0=(const float*)d_in[3];
    const float* bhh0=(const float*)d_in[4];
    const float* Wih1=(const float*)d_in[5];
    const float* Whh1=(const float*)d_in[6];
    const float* bih1=(const float*)d_in[7];
    const float* bhh1=(const float*)d_in[8];
    const float* W1=(const float*)d_in[9];
    const float* b1=(const float*)d_in[10];
    const float* W2=(const float*)d_in[11];
    const float* b2=(const float*)d_in[12];
    const float* W3=(const float*)d_in[13];
    const float* b3=(const float*)d_in[14];
    float* out=(float*)d_out;

    const int smem0=(SRR*GSZ+KP0*12+8*GSZ)*4;          // 219,904 B
    const int smem1=(SRR*GSZ+KP1*12+8*GSZ)*4;          // 219,136 B
    const int smemg=(128*BS2 + 2*64*AS2)*2;            // 167,936 B
    cudaFuncSetAttribute((const void*)lstm_kernel<0>,cudaFuncAttributeMaxDynamicSharedMemorySize,smem0);
    cudaFuncSetAttribute((const void*)lstm_kernel<1>,cudaFuncAttributeMaxDynamicSharedMemorySize,smem1);
    cudaFuncSetAttribute((const void*)xp_tc2_kernel,cudaFuncAttributeMaxDynamicSharedMemorySize,smemg);

    int tot=(KP0+KP1)*GSZ+2*GSZ+GSZ*384;
    prep_kernel<<<(tot+255)/256,256>>>(Wih0,Whh0,bih0,bhh0,Wih1,Whh1,bih1,bhh1);
    lstm_kernel<0><<<NBLK,256,smem0>>>(x);
    xp_tc2_kernel<<<dim3(128,4),256,smemg>>>();
    lstm_kernel<1><<<NBLK,256,smem1>>>(nullptr);
    head_kernel<<<BATCH,64>>>(W1,b1,W2,b2,W3,b3,out);
}

// round 14
// speedup vs baseline: 1.2752x; 1.0208x over previous
#include <cuda_runtime.h>
#include <cuda_bf16.h>
#include <cstdint>
#include <cstddef>

#define HID 128
#define GSZ 512
#define BATCH 1024
#define TLEN 512
#define DIN 12
#define KP0 144
#define KP1 128
#define SRR 96
#define BT 8
#define NBLK 128
#define MROWS (TLEN*BATCH)
#define AS2 264      // A smem stride (bf16)
#define BS2 392      // B smem stride (bf16)
#define NTILE 64     // 64-row A tiles per CTA

typedef unsigned long long ull;

// ---------------- device globals ----------------
__device__ float g_W0T[KP0*GSZ];                     // [k][j] L0 weights (x|h concat)
__device__ float g_W1T[KP1*GSZ];                     // [k][j] L1 W_hh only
__device__ float g_bias0[GSZ];
__device__ float g_bias1[GSZ];
__device__ __nv_bfloat16 g_h1s[(size_t)MROWS*256];   // h1 [row][hi128|lo128]
__device__ __nv_bfloat16 g_BE[GSZ*384];              // W_ih1 ext [n][384] = wh|wh|wl
__device__ float g_xp1[(size_t)MROWS*GSZ];           // h1@Wih1^T + b1, [t][b][512]
__device__ float g_h2[BATCH*HID];

// ---------------- helpers ----------------
__device__ __forceinline__ ull dup2(float x){ull d;asm("mov.b64 %0,{%1,%1};":"=l"(d):"f"(x));return d;}
__device__ __forceinline__ ull pk2(float x,float y){ull d;asm("mov.b64 %0,{%1,%2};":"=l"(d):"f"(x),"f"(y));return d;}
__device__ __forceinline__ ull fma2(ull a,ull b,ull c){ull d;asm("fma.rn.f32x2 %0,%1,%2,%3;":"=l"(d):"l"(a),"l"(b),"l"(c));return d;}
__device__ __forceinline__ float2 unp(ull v){float2 r;asm("mov.b64 {%0,%1},%2;":"=f"(r.x),"=f"(r.y):"l"(v));return r;}
__device__ __forceinline__ float sigm(float x){return __fdividef(1.0f,1.0f+__expf(-x));}
__device__ __forceinline__ float tanh_f(float x){return __fdividef(2.0f,1.0f+__expf(-2.0f*x))-1.0f;}
__device__ __forceinline__ uint32_t smem_u32(const void* p){
    uint32_t a;
    asm("{ .reg .u64 t; cvta.to.shared.u64 t, %1; cvt.u32.u64 %0, t; }":"=r"(a):"l"(p));
    return a;
}

#define MMA(d,a,b0,b1) \
    asm volatile("mma.sync.aligned.m16n8k16.row.col.f32.bf16.bf16.f32 " \
        "{%0,%1,%2,%3},{%4,%5,%6,%7},{%8,%9},{%0,%1,%2,%3};" \
        : "+f"((d)[0]),"+f"((d)[1]),"+f"((d)[2]),"+f"((d)[3]) \
        : "r"((a)[0]),"r"((a)[1]),"r"((a)[2]),"r"((a)[3]),"r"(b0),"r"(b1))

#define LDSM4(r0,r1,r2,r3,addr) \
    asm volatile("ldmatrix.sync.aligned.m8n8.x4.shared.b16 {%0,%1,%2,%3}, [%4];" \
        : "=r"(r0),"=r"(r1),"=r"(r2),"=r"(r3) : "r"(addr))

#define CP16(dst,src) \
    asm volatile("cp.async.cg.shared.global [%0], [%1], 16;"::"r"(dst),"l"(src))
#define CP_COMMIT() asm volatile("cp.async.commit_group;" ::: "memory")
#define CP_WAIT0()  asm volatile("cp.async.wait_group 0;" ::: "memory")

// one weight row (2 gate cols) x 8 batch rows -> 8 f32x2 accumulators
#define FMA_ROW(W2V,KIDX) do{ \
    ull w0=dup2((W2V).x), w1=dup2((W2V).y); \
    ulonglong2 vA=*(const ulonglong2*)&v_s[(KIDX)*12]; \
    ulonglong2 vB=*(const ulonglong2*)&v_s[(KIDX)*12+4]; \
    a0=fma2(w0,vA.x,a0); a1=fma2(w0,vA.y,a1); \
    a2=fma2(w0,vB.x,a2); a3=fma2(w0,vB.y,a3); \
    a4=fma2(w1,vA.x,a4); a5=fma2(w1,vA.y,a5); \
    a6=fma2(w1,vB.x,a6); a7=fma2(w1,vB.y,a7); }while(0)

// ---------------- prep ----------------
__global__ void prep_kernel(const float* __restrict__ Wih0,const float* __restrict__ Whh0,
                            const float* __restrict__ bih0,const float* __restrict__ bhh0,
                            const float* __restrict__ Wih1,const float* __restrict__ Whh1,
                            const float* __restrict__ bih1,const float* __restrict__ bhh1){
    int i = blockIdx.x*blockDim.x + threadIdx.x;
    const int S0=KP0*GSZ, S1=S0+KP1*GSZ, S2=S1+GSZ, S3=S2+GSZ, S4=S3+GSZ*384;
    if(i<S0){
        int k=i/GSZ, j=i%GSZ; float v=0.f;
        if(k<DIN) v=Wih0[j*DIN+k]; else if(k<DIN+HID) v=Whh0[j*HID+(k-DIN)];
        g_W0T[i]=v;
    }else if(i<S1){
        int i2=i-S0; int k=i2/GSZ, j=i2%GSZ;
        g_W1T[i2]=Whh1[j*HID+k];
    }else if(i<S2){ int j=i-S1; g_bias0[j]=bih0[j]+bhh0[j]; }
    else if(i<S3){ int j=i-S2; g_bias1[j]=bih1[j]+bhh1[j]; }
    else if(i<S4){
        int i2=i-S3; int n=i2/384, kp=i2%384, k=kp&127;
        float w=Wih1[n*HID+k];
        __nv_bfloat16 hi=__float2bfloat16(w);
        g_BE[i2] = (kp<256)? hi : __float2bfloat16(w-__bfloat162float(hi));
    }
}

// prefetch one 64-row A tile (64 x 256 bf16 = 32KB) via cp.async
__device__ __forceinline__ void prefetchA(size_t mt, __nv_bfloat16* buf, int tid){
    const char* src = (const char*)(g_h1s + mt*64*256);
    uint32_t dbase = smem_u32(buf);
#pragma unroll
    for(int c=0;c<8;c++){
        int chunk = tid + c*256;
        int r = chunk>>5, col16 = chunk&31;
        uint32_t d = dbase + (uint32_t)(r*AS2*2 + col16*16);
        CP16(d, src + r*512 + col16*16);
    }
    CP_COMMIT();
}

// ---------------- xp1 GEMM: ldmatrix + mma.sync, MMA-bound inner loop ----------------
// Grid (128 msets, 4 ny). Per CTA: B tile (128n x 384k) smem-resident; 64 A tiles
// (64 rows) double-buffered via cp.async. Split-3 exact: A hi|lo|hi vs B wh|wh|wl.
// Warp tile: 2 m-tiles x 4 n-tiles. Per kc: 2 A-LDSM.x4 + 2 B-LDSM.x4 + 8 MMA.
__global__ void __launch_bounds__(256,1) xp_tc3_kernel(){
    extern __shared__ __nv_bfloat16 sh[];
    __nv_bfloat16* Bs = sh;                  // [128][BS2] = 100,352B
    __nv_bfloat16* A0 = sh + 128*BS2;        // [64][AS2]  =  33,792B
    __nv_bfloat16* A1 = A0 + 64*AS2;
    const int tid=threadIdx.x, wid=tid>>5, lane=tid&31;
    const int g=lane>>2, tq=lane&3;
    const int mset=blockIdx.x, ny=blockIdx.y;

    // B tile once
    {
        const float4* bsrc=(const float4*)(g_BE + (size_t)ny*128*384);
        for(int i=tid;i<6144;i+=256){
            int n=i/48, kq=i%48;
            *(float4*)(Bs + n*BS2 + kq*8)=bsrc[i];
        }
    }
    const int mh = (wid&1)*32;      // warp m-half within 64-row tile
    const int nq = (wid>>1)*32;     // warp n-quarter within 128

    float bx[4], by[4];
#pragma unroll
    for(int ni=0;ni<4;ni++){
        int col=ny*128+nq+ni*8+2*tq;
        bx[ni]=g_bias1[col]; by[ni]=g_bias1[col+1];
    }

    // per-thread LDSM addresses
    // A: row = mh + mi*16 + (lane&15), col-half = (lane>>4)*8 (+ks per kc)
    const uint32_t aRowOff = (uint32_t)((mh + (lane&15))*AS2*2 + ((lane>>4)*8)*2);
    // B: row = nq + pair*16 + (lane&7) + (lane>>4)*8, k-half = ((lane>>3)&1)*8 (+kb)
    const uint32_t bBase = smem_u32(Bs);
    uint32_t bAddr[2];
#pragma unroll
    for(int pr=0;pr<2;pr++)
        bAddr[pr] = bBase + (uint32_t)((nq + pr*16 + (lane&7) + (lane>>4)*8)*BS2*2
                                       + (((lane>>3)&1)*8)*2);

    prefetchA((size_t)mset, A0, tid);
    __syncthreads();    // B visible

#pragma unroll 1
    for(int i=0;i<NTILE;i++){
        __nv_bfloat16* Ac = (i&1)? A1 : A0;
        CP_WAIT0();
        __syncthreads();                        // A tile i visible
        if(i+1<NTILE)
            prefetchA((size_t)mset + 128*(size_t)(i+1), (i&1)? A0 : A1, tid);

        const uint32_t aBase = smem_u32(Ac) + aRowOff;
        float acc[2][4][4];
#pragma unroll
        for(int mi=0;mi<2;mi++)
#pragma unroll
            for(int ni=0;ni<4;ni++)
#pragma unroll
                for(int q=0;q<4;q++) acc[mi][ni][q]=0.f;

#pragma unroll 4
        for(int kc=0;kc<24;kc++){
            int ks=(kc<8)?kc*16:(kc<16)?(128+(kc-8)*16):((kc-16)*16);
            int kb=kc*16;
            uint32_t a[2][4];
#pragma unroll
            for(int mi=0;mi<2;mi++)
                LDSM4(a[mi][0],a[mi][1],a[mi][2],a[mi][3],
                      aBase + (uint32_t)(mi*16*AS2*2 + ks*2));
            uint32_t b[2][4];
#pragma unroll
            for(int pr=0;pr<2;pr++)
                LDSM4(b[pr][0],b[pr][1],b[pr][2],b[pr][3],
                      bAddr[pr] + (uint32_t)(kb*2));
#pragma unroll
            for(int mi=0;mi<2;mi++){
                MMA(acc[mi][0],a[mi],b[0][0],b[0][1]);
                MMA(acc[mi][1],a[mi],b[0][2],b[0][3]);
                MMA(acc[mi][2],a[mi],b[1][0],b[1][1]);
                MMA(acc[mi][3],a[mi],b[1][2],b[1][3]);
            }
        }
        // epilogue
        {
            int colb=ny*128+nq;
#pragma unroll
            for(int mi=0;mi<2;mi++){
                size_t r0=((size_t)mset + 128*(size_t)i)*64 + mh + mi*16 + g;
#pragma unroll
                for(int ni=0;ni<4;ni++){
                    int col=colb+ni*8+2*tq;
                    *(float2*)&g_xp1[r0*GSZ+col]     = make_float2(acc[mi][ni][0]+bx[ni], acc[mi][ni][1]+by[ni]);
                    *(float2*)&g_xp1[(r0+8)*GSZ+col] = make_float2(acc[mi][ni][2]+bx[ni], acc[mi][ni][3]+by[ni]);
                }
            }
        }
        __syncthreads();   // all warps done with Ac before overwrite
    }
}

// ---------------- fused LSTM scan (R8/R13-exact) ----------------
template <int LAYER>
__global__ void __launch_bounds__(256,1) lstm_kernel(const float* __restrict__ x){
    constexpr int KP=(LAYER==0)?KP0:KP1;
    constexpr int PRM=KP-SRR;                 // 48 / 32
    constexpr int KOFF=(LAYER==0)?DIN:0;
    const float* __restrict__ WT=(LAYER==0)?g_W0T:g_W1T;

    extern __shared__ float smem[];
    float* w_s=smem;                 // SRR*512
    float* v_s=w_s+SRR*GSZ;          // KP*12
    float* g_s=v_s+KP*12;            // 8*512

    const int tid=threadIdx.x;
    const int b0=blockIdx.x*BT;
    const int j0=2*tid;
    {
        const float2* src=(const float2*)WT;
        float2* dst=(float2*)w_s;
        for(int i=tid;i<SRR*GSZ/2;i+=256) dst[i]=src[i];
    }
    for(int i=tid;i<KP*12;i+=256) v_s[i]=0.f;

    float2 pbuf[PRM];
#pragma unroll
    for(int i=0;i<PRM;i++) pbuf[i]=*(const float2*)&WT[(SRR+i)*GSZ+j0];

    ull bxd=0, byd=0;
    if(LAYER==0){
        float2 bj=*(const float2*)&g_bias0[j0];
        bxd=dup2(bj.x); byd=dup2(bj.y);
    }
    const int ub=tid>>5, um=tid&31;
    float c_r[4]={0.f,0.f,0.f,0.f};

    for(int t=0;t<TLEN;t++){
        float xstage=0.f; float2 xpr[8];
        int st_r=0, st_d=0;
        if(LAYER==0){
            if(tid<96){ st_r=tid/12; st_d=tid%12;
                xstage=x[(((size_t)(b0+st_r))*TLEN+t)*DIN+st_d]; }
        }else{
            const float* xpb=g_xp1+(((size_t)t)*BATCH+b0)*GSZ+j0;
#pragma unroll
            for(int b=0;b<8;b++) xpr[b]=*(const float2*)(xpb+(size_t)b*GSZ);
        }
        if(t>0){
#pragma unroll
            for(int q=0;q<4;q++){
                int m=um+32*q;
                float iv=sigm(g_s[ub*GSZ+m]);
                float fv=sigm(g_s[ub*GSZ+128+m]);
                float gv=tanh_f(g_s[ub*GSZ+256+m]);
                float ov=sigm(g_s[ub*GSZ+384+m]);
                float c=fv*c_r[q]+iv*gv; c_r[q]=c;
                float h=ov*tanh_f(c);
                v_s[(KOFF+m)*12+ub]=h;
                if(LAYER==0){
                    size_t row=((size_t)(t-1))*BATCH+b0+ub;
                    __nv_bfloat16 hb=__float2bfloat16(h);
                    g_h1s[row*256+m]=hb;
                    g_h1s[row*256+128+m]=__float2bfloat16(h-__bfloat162float(hb));
                }
            }
        }
        if(LAYER==0){ if(tid<96) v_s[st_d*12+st_r]=xstage; }
        __syncthreads();

        ull a0,a1,a2,a3,a4,a5,a6,a7;
        if(LAYER==0){ a0=bxd;a1=bxd;a2=bxd;a3=bxd; a4=byd;a5=byd;a6=byd;a7=byd; }
        else{
            a0=pk2(xpr[0].x,xpr[1].x); a1=pk2(xpr[2].x,xpr[3].x);
            a2=pk2(xpr[4].x,xpr[5].x); a3=pk2(xpr[6].x,xpr[7].x);
            a4=pk2(xpr[0].y,xpr[1].y); a5=pk2(xpr[2].y,xpr[3].y);
            a6=pk2(xpr[4].y,xpr[5].y); a7=pk2(xpr[6].y,xpr[7].y);
        }
#pragma unroll 4
        for(int k=0;k<SRR;k++){
            float2 w=*(const float2*)&w_s[k*GSZ+j0];
            FMA_ROW(w,k);
        }
#pragma unroll
        for(int i=0;i<PRM;i++) FMA_ROW(pbuf[i],SRR+i);
        {
            ull ac0[4]={a0,a1,a2,a3}, ac1[4]={a4,a5,a6,a7};
#pragma unroll
            for(int p=0;p<4;p++){
                float2 u0=unp(ac0[p]), u1=unp(ac1[p]);
                *(float2*)&g_s[(2*p)*GSZ+j0]  =make_float2(u0.x,u1.x);
                *(float2*)&g_s[(2*p+1)*GSZ+j0]=make_float2(u0.y,u1.y);
            }
        }
        __syncthreads();
    }
#pragma unroll
    for(int q=0;q<4;q++){
        int m=um+32*q;
        float iv=sigm(g_s[ub*GSZ+m]);
        float fv=sigm(g_s[ub*GSZ+128+m]);
        float gv=tanh_f(g_s[ub*GSZ+256+m]);
        float ov=sigm(g_s[ub*GSZ+384+m]);
        float c=fv*c_r[q]+iv*gv;
        float h=ov*tanh_f(c);
        if(LAYER==0){
            size_t row=((size_t)(TLEN-1))*BATCH+b0+ub;
            __nv_bfloat16 hb=__float2bfloat16(h);
            g_h1s[row*256+m]=hb;
            g_h1s[row*256+128+m]=__float2bfloat16(h-__bfloat162float(hb));
        }else g_h2[(b0+ub)*HID+m]=h;
    }
}

// ---------------- MLP head ----------------
__global__ void head_kernel(const float* __restrict__ W1,const float* __restrict__ b1,
                            const float* __restrict__ W2,const float* __restrict__ b2,
                            const float* __restrict__ W3,const float* __restrict__ b3,
                            float* __restrict__ out){
    __shared__ float hrow[HID]; __shared__ float z1[64]; __shared__ float z2[32];
    int b=blockIdx.x, tid=threadIdx.x;
    hrow[tid]=g_h2[b*HID+tid];
    hrow[tid+64]=g_h2[b*HID+tid+64];
    __syncthreads();
    {
        float s=b1[tid];
        const float* w=&W1[tid*HID];
#pragma unroll 8
        for(int k=0;k<HID;k++) s+=w[k]*hrow[k];
        z1[tid]=fmaxf(s,0.f);
    }
    __syncthreads();
    if(tid<32){
        float s=b2[tid];
        const float* w=&W2[tid*64];
#pragma unroll 8
        for(int k=0;k<64;k++) s+=w[k]*z1[k];
        z2[tid]=fmaxf(s,0.f);
    }
    __syncthreads();
    if(tid<2){
        float s=b3[tid];
        const float* w=&W3[tid*32];
#pragma unroll
        for(int k=0;k<32;k++) s+=w[k]*z2[k];
        out[b*2+tid]=s;
    }
}

// ---------------- launch ----------------
extern "C" void kernel_launch(void* const* d_in, const int* in_sizes, int n_in,
                              void* d_out, int out_size){
    const float* x   =(const float*)d_in[0];
    const float* Wih0=(const float*)d_in[1];
    const float* Whh0=(const float*)d_in[2];
    const float* bih0=(const float*)d_in[3];
    const float* bhh0=(const float*)d_in[4];
    const float* Wih1=(const float*)d_in[5];
    const float* Whh1=(const float*)d_in[6];
    const float* bih1=(const float*)d_in[7];
    const float* bhh1=(const float*)d_in[8];
    const float* W1=(const float*)d_in[9];
    const float* b1=(const float*)d_in[10];
    const float* W2=(const float*)d_in[11];
    const float* b2=(const float*)d_in[12];
    const float* W3=(const float*)d_in[13];
    const float* b3=(const float*)d_in[14];
    float* out=(float*)d_out;

    const int smem0=(SRR*GSZ+KP0*12+8*GSZ)*4;          // 219,904 B
    const int smem1=(SRR*GSZ+KP1*12+8*GSZ)*4;          // 219,136 B
    const int smemg=(128*BS2 + 2*64*AS2)*2;            // 167,936 B
    cudaFuncSetAttribute((const void*)lstm_kernel<0>,cudaFuncAttributeMaxDynamicSharedMemorySize,smem0);
    cudaFuncSetAttribute((const void*)lstm_kernel<1>,cudaFuncAttributeMaxDynamicSharedMemorySize,smem1);
    cudaFuncSetAttribute((const void*)xp_tc3_kernel,cudaFuncAttributeMaxDynamicSharedMemorySize,smemg);

    int tot=(KP0+KP1)*GSZ+2*GSZ+GSZ*384;
    prep_kernel<<<(tot+255)/256,256>>>(Wih0,Whh0,bih0,bhh0,Wih1,Whh1,bih1,bhh1);
    lstm_kernel<0><<<NBLK,256,smem0>>>(x);
    xp_tc3_kernel<<<dim3(128,4),256,smemg>>>();
    lstm_kernel<1><<<NBLK,256,smem1>>>(nullptr);
    head_kernel<<<BATCH,64>>>(W1,b1,W2,b2,W3,b3,out);
}

// round 16
// speedup vs baseline: 1.5554x; 1.2197x over previous
#include <cuda_runtime.h>
#include <cuda_bf16.h>
#include <cstdint>
#include <cstddef>

#define HID 128
#define GSZ 512
#define BATCH 1024
#define TLEN 512
#define DIN 12
#define KP0 144
#define SRR 96
#define BT 8
#define NBLK 128
#define MROWS (TLEN*BATCH)
#define AS2 264      // gemm A smem stride (bf16)
#define BS2 392      // gemm B smem stride (bf16)
#define NTILE 64
#define ASTR 136     // scan1 A_s bf16 row stride
#define BUFS 516     // scan1 gate/xp fp32 row stride

typedef unsigned long long ull;

extern __shared__ char dynsm[];   // single dynamic-smem declaration for all kernels

// ---------------- device globals ----------------
__device__ float g_W0T[KP0*GSZ];                     // [k][j] L0 weights (x|h concat)
__device__ float g_bias0[GSZ];
__device__ float g_bias1[GSZ];
__device__ __nv_bfloat16 g_h1s[(size_t)MROWS*256];   // h1 [row][hi128|lo128]
__device__ __nv_bfloat16 g_BE[GSZ*384];              // W_ih1 ext [n][384] = wh|wh|wl
__device__ ull g_Wpk[32768];                         // packed W_hh1 frag planes (hi|lo)
__device__ float g_xp1[(size_t)MROWS*GSZ];           // h1@Wih1^T + b1, [t][b][512]
__device__ float g_h2[BATCH*HID];

// ---------------- helpers ----------------
__device__ __forceinline__ ull dup2(float x){ull d;asm("mov.b64 %0,{%1,%1};":"=l"(d):"f"(x));return d;}
__device__ __forceinline__ ull fma2(ull a,ull b,ull c){ull d;asm("fma.rn.f32x2 %0,%1,%2,%3;":"=l"(d):"l"(a),"l"(b),"l"(c));return d;}
__device__ __forceinline__ float2 unp(ull v){float2 r;asm("mov.b64 {%0,%1},%2;":"=f"(r.x),"=f"(r.y):"l"(v));return r;}
__device__ __forceinline__ float sigm(float x){return __fdividef(1.0f,1.0f+__expf(-x));}
__device__ __forceinline__ float tanh_f(float x){return __fdividef(2.0f,1.0f+__expf(-2.0f*x))-1.0f;}
__device__ __forceinline__ uint32_t smem_u32(const void* p){
    uint32_t a;
    asm("{ .reg .u64 t; cvta.to.shared.u64 t, %1; cvt.u32.u64 %0, t; }":"=r"(a):"l"(p));
    return a;
}
__device__ __forceinline__ uint32_t pkbf(float a, float b){
    __nv_bfloat16 ha=__float2bfloat16(a), hb=__float2bfloat16(b);
    return (uint32_t)__bfloat16_as_ushort(ha) | ((uint32_t)__bfloat16_as_ushort(hb)<<16);
}

#define MMA(d,a,b0,b1) \
    asm volatile("mma.sync.aligned.m16n8k16.row.col.f32.bf16.bf16.f32 " \
        "{%0,%1,%2,%3},{%4,%5,%6,%7},{%8,%9},{%0,%1,%2,%3};" \
        : "+f"((d)[0]),"+f"((d)[1]),"+f"((d)[2]),"+f"((d)[3]) \
        : "r"((a)[0]),"r"((a)[1]),"r"((a)[2]),"r"((a)[3]),"r"(b0),"r"(b1))

#define LDSM4(r0,r1,r2,r3,addr) \
    asm volatile("ldmatrix.sync.aligned.m8n8.x4.shared.b16 {%0,%1,%2,%3}, [%4];" \
        : "=r"(r0),"=r"(r1),"=r"(r2),"=r"(r3) : "r"(addr))

#define CP16(dst,src) \
    asm volatile("cp.async.cg.shared.global [%0], [%1], 16;"::"r"(dst),"l"(src))
#define CP_COMMIT() asm volatile("cp.async.commit_group;" ::: "memory")
#define CP_WAIT0()  asm volatile("cp.async.wait_group 0;" ::: "memory")

#define FMA_ROW(W2V,KIDX) do{ \
    ull w0=dup2((W2V).x), w1=dup2((W2V).y); \
    ulonglong2 vA=*(const ulonglong2*)&v_s[(KIDX)*12]; \
    ulonglong2 vB=*(const ulonglong2*)&v_s[(KIDX)*12+4]; \
    a0=fma2(w0,vA.x,a0); a1=fma2(w0,vA.y,a1); \
    a2=fma2(w0,vB.x,a2); a3=fma2(w0,vB.y,a3); \
    a4=fma2(w1,vA.x,a4); a5=fma2(w1,vA.y,a5); \
    a6=fma2(w1,vB.x,a6); a7=fma2(w1,vB.y,a7); }while(0)

// ---------------- prep ----------------
__global__ void prep_kernel(const float* __restrict__ Wih0,const float* __restrict__ Whh0,
                            const float* __restrict__ bih0,const float* __restrict__ bhh0,
                            const float* __restrict__ Wih1,const float* __restrict__ Whh1,
                            const float* __restrict__ bih1,const float* __restrict__ bhh1){
    int i = blockIdx.x*blockDim.x + threadIdx.x;
    const int S0=KP0*GSZ, S1=S0+GSZ, S2=S1+GSZ, S3=S2+GSZ*384, S4=S3+32768;
    if(i<S0){
        int k=i/GSZ, j=i%GSZ; float v=0.f;
        if(k<DIN) v=Wih0[j*DIN+k]; else if(k<DIN+HID) v=Whh0[j*HID+(k-DIN)];
        g_W0T[i]=v;
    }else if(i<S1){ int j=i-S0; g_bias0[j]=bih0[j]+bhh0[j]; }
    else if(i<S2){ int j=i-S1; g_bias1[j]=bih1[j]+bhh1[j]; }
    else if(i<S3){
        int i2=i-S2; int n=i2/384, kp=i2%384, k=kp&127;
        float w=Wih1[n*HID+k];
        __nv_bfloat16 hi=__float2bfloat16(w);
        g_BE[i2] = (kp<256)? hi : __float2bfloat16(w-__bfloat162float(hi));
    }else if(i<S4){
        // packed W_hh1 b-frags (canonical m16n8k16 B layout, validated R11)
        int u=i-S3;
        int lane=u&31, ni=(u>>5)&7, c=(u>>8)&7, p=(u>>11)&1, w=(u>>12)&7;
        int g=lane>>2, tq=lane&3;
        int n = w*64 + ni*8 + g;
        int k0 = c*16 + 2*tq;
        float v[4];
#pragma unroll
        for(int e=0;e<4;e++){
            int k = k0 + (e>>1)*8 + (e&1);
            float x = Whh1[n*HID + k];
            __nv_bfloat16 hi = __float2bfloat16(x);
            v[e] = (p==0)? __bfloat162float(hi) : (x - __bfloat162float(hi));
        }
        g_Wpk[u] = (ull)pkbf(v[0],v[1]) | ((ull)pkbf(v[2],v[3])<<32);
    }
}

// prefetch one 64-row A tile via cp.async (gemm)
__device__ __forceinline__ void prefetchA(size_t mt, __nv_bfloat16* buf, int tid){
    const char* src = (const char*)(g_h1s + mt*64*256);
    uint32_t dbase = smem_u32(buf);
#pragma unroll
    for(int c=0;c<8;c++){
        int chunk = tid + c*256;
        int r = chunk>>5, col16 = chunk&31;
        CP16(dbase + (uint32_t)(r*AS2*2 + col16*16), src + r*512 + col16*16);
    }
    CP_COMMIT();
}

// ---------------- xp1 GEMM (R14-exact: ldmatrix + mma.sync, pipelined) ----------------
__global__ void __launch_bounds__(256,1) xp_tc3_kernel(){
    __nv_bfloat16* Bs = (__nv_bfloat16*)dynsm;
    __nv_bfloat16* A0 = Bs + 128*BS2;
    __nv_bfloat16* A1 = A0 + 64*AS2;
    const int tid=threadIdx.x, wid=tid>>5, lane=tid&31;
    const int g=lane>>2, tq=lane&3;
    const int mset=blockIdx.x, ny=blockIdx.y;
    {
        const float4* bsrc=(const float4*)(g_BE + (size_t)ny*128*384);
        for(int i=tid;i<6144;i+=256){
            int n=i/48, kq=i%48;
            *(float4*)(Bs + n*BS2 + kq*8)=bsrc[i];
        }
    }
    const int mh = (wid&1)*32;
    const int nq = (wid>>1)*32;
    float bx[4], by[4];
#pragma unroll
    for(int ni=0;ni<4;ni++){
        int col=ny*128+nq+ni*8+2*tq;
        bx[ni]=g_bias1[col]; by[ni]=g_bias1[col+1];
    }
    const uint32_t aRowOff = (uint32_t)((mh + (lane&15))*AS2*2 + ((lane>>4)*8)*2);
    const uint32_t bBase = smem_u32(Bs);
    uint32_t bAddr[2];
#pragma unroll
    for(int pr=0;pr<2;pr++)
        bAddr[pr] = bBase + (uint32_t)((nq + pr*16 + (lane&7) + (lane>>4)*8)*BS2*2
                                       + (((lane>>3)&1)*8)*2);
    prefetchA((size_t)mset, A0, tid);
    __syncthreads();
#pragma unroll 1
    for(int i=0;i<NTILE;i++){
        __nv_bfloat16* Ac = (i&1)? A1 : A0;
        CP_WAIT0();
        __syncthreads();
        if(i+1<NTILE)
            prefetchA((size_t)mset + 128*(size_t)(i+1), (i&1)? A0 : A1, tid);
        const uint32_t aBase = smem_u32(Ac) + aRowOff;
        float acc[2][4][4];
#pragma unroll
        for(int mi=0;mi<2;mi++)
#pragma unroll
            for(int ni=0;ni<4;ni++)
#pragma unroll
                for(int q=0;q<4;q++) acc[mi][ni][q]=0.f;
#pragma unroll 4
        for(int kc=0;kc<24;kc++){
            int ks=(kc<8)?kc*16:(kc<16)?(128+(kc-8)*16):((kc-16)*16);
            int kb=kc*16;
            uint32_t a[2][4];
#pragma unroll
            for(int mi=0;mi<2;mi++)
                LDSM4(a[mi][0],a[mi][1],a[mi][2],a[mi][3],
                      aBase + (uint32_t)(mi*16*AS2*2 + ks*2));
            uint32_t b[2][4];
#pragma unroll
            for(int pr=0;pr<2;pr++)
                LDSM4(b[pr][0],b[pr][1],b[pr][2],b[pr][3],
                      bAddr[pr] + (uint32_t)(kb*2));
#pragma unroll
            for(int mi=0;mi<2;mi++){
                MMA(acc[mi][0],a[mi],b[0][0],b[0][1]);
                MMA(acc[mi][1],a[mi],b[0][2],b[0][3]);
                MMA(acc[mi][2],a[mi],b[1][0],b[1][1]);
                MMA(acc[mi][3],a[mi],b[1][2],b[1][3]);
            }
        }
        {
            int colb=ny*128+nq;
#pragma unroll
            for(int mi=0;mi<2;mi++){
                size_t r0=((size_t)mset + 128*(size_t)i)*64 + mh + mi*16 + g;
#pragma unroll
                for(int ni=0;ni<4;ni++){
                    int col=colb+ni*8+2*tq;
                    *(float2*)&g_xp1[r0*GSZ+col]     = make_float2(acc[mi][ni][0]+bx[ni], acc[mi][ni][1]+by[ni]);
                    *(float2*)&g_xp1[(r0+8)*GSZ+col] = make_float2(acc[mi][ni][2]+bx[ni], acc[mi][ni][3]+by[ni]);
                }
            }
        }
        __syncthreads();
    }
}

// ---------------- layer-0 scan (R14-exact FFMA) ----------------
__global__ void __launch_bounds__(256,1) lstm0_kernel(const float* __restrict__ x){
    constexpr int KP=KP0, PRM=KP0-SRR, KOFF=DIN;
    const float* __restrict__ WT=g_W0T;
    float* w_s=(float*)dynsm;
    float* v_s=w_s+SRR*GSZ;
    float* g_s=v_s+KP*12;
    const int tid=threadIdx.x;
    const int b0=blockIdx.x*BT;
    const int j0=2*tid;
    {
        const float2* src=(const float2*)WT;
        float2* dst=(float2*)w_s;
        for(int i=tid;i<SRR*GSZ/2;i+=256) dst[i]=src[i];
    }
    for(int i=tid;i<KP*12;i+=256) v_s[i]=0.f;
    float2 pbuf[PRM];
#pragma unroll
    for(int i=0;i<PRM;i++) pbuf[i]=*(const float2*)&WT[(SRR+i)*GSZ+j0];
    float2 bj=*(const float2*)&g_bias0[j0];
    ull bxd=dup2(bj.x), byd=dup2(bj.y);
    const int ub=tid>>5, um=tid&31;
    float c_r[4]={0.f,0.f,0.f,0.f};
    for(int t=0;t<TLEN;t++){
        float xstage=0.f; int st_r=0, st_d=0;
        if(tid<96){ st_r=tid/12; st_d=tid%12;
            xstage=x[(((size_t)(b0+st_r))*TLEN+t)*DIN+st_d]; }
        if(t>0){
#pragma unroll
            for(int q=0;q<4;q++){
                int m=um+32*q;
                float iv=sigm(g_s[ub*GSZ+m]);
                float fv=sigm(g_s[ub*GSZ+128+m]);
                float gv=tanh_f(g_s[ub*GSZ+256+m]);
                float ov=sigm(g_s[ub*GSZ+384+m]);
                float c=fv*c_r[q]+iv*gv; c_r[q]=c;
                float h=ov*tanh_f(c);
                v_s[(KOFF+m)*12+ub]=h;
                size_t row=((size_t)(t-1))*BATCH+b0+ub;
                __nv_bfloat16 hb=__float2bfloat16(h);
                g_h1s[row*256+m]=hb;
                g_h1s[row*256+128+m]=__float2bfloat16(h-__bfloat162float(hb));
            }
        }
        if(tid<96) v_s[st_d*12+st_r]=xstage;
        __syncthreads();
        ull a0=bxd,a1=bxd,a2=bxd,a3=bxd,a4=byd,a5=byd,a6=byd,a7=byd;
#pragma unroll 4
        for(int k=0;k<SRR;k++){
            float2 w=*(const float2*)&w_s[k*GSZ+j0];
            FMA_ROW(w,k);
        }
#pragma unroll
        for(int i=0;i<PRM;i++) FMA_ROW(pbuf[i],SRR+i);
        {
            ull ac0[4]={a0,a1,a2,a3}, ac1[4]={a4,a5,a6,a7};
#pragma unroll
            for(int p=0;p<4;p++){
                float2 u0=unp(ac0[p]), u1=unp(ac1[p]);
                *(float2*)&g_s[(2*p)*GSZ+j0]  =make_float2(u0.x,u1.x);
                *(float2*)&g_s[(2*p+1)*GSZ+j0]=make_float2(u0.y,u1.y);
            }
        }
        __syncthreads();
    }
#pragma unroll
    for(int q=0;q<4;q++){
        int m=um+32*q;
        float iv=sigm(g_s[ub*GSZ+m]);
        float fv=sigm(g_s[ub*GSZ+128+m]);
        float gv=tanh_f(g_s[ub*GSZ+256+m]);
        float ov=sigm(g_s[ub*GSZ+384+m]);
        float c=fv*c_r[q]+iv*gv;
        float h=ov*tanh_f(c);
        size_t row=((size_t)(TLEN-1))*BATCH+b0+ub;
        __nv_bfloat16 hb=__float2bfloat16(h);
        g_h1s[row*256+m]=hb;
        g_h1s[row*256+128+m]=__float2bfloat16(h-__bfloat162float(hb));
    }
}

// ---------------- layer-1 scan on tensor cores ----------------
// 128 blocks x 256 threads; 8 batch rows. A_s = [h_hi(8); h_lo(8)] rows, M=16 MMA.
// Per step: 8 k-chunks x 8 n-tiles x (hi+lo planes) = 128 MMA/warp. A via ldmatrix.x4.
// B frags: hi chunks 0-7 + lo chunks 0-3 in smem (per-lane packed, conflict-free);
// lo chunks 4-7 in 64 persistent registers.
__global__ void __launch_bounds__(256,1) lstm1_tc_kernel(){
    ull*  ws  = (ull*)dynsm;                               // 196,608 B
    __nv_bfloat16* A_s = (__nv_bfloat16*)(dynsm + 196608); // 4,352 B
    float* buf = (float*)(dynsm + 196608 + 4352);          // 16,512 B

    const int tid = threadIdx.x;
    const int w = tid>>5, lane = tid&31, g = lane>>2, tq = lane&3;
    const int b0 = blockIdx.x*BT;

    for(int i=lane;i<3072;i+=32){
        int s=i>>8, rem=i&255;
        ws[w*3072+i] = g_Wpk[w*4096 + (s<8 ? s*256 : 2048+(s-8)*256) + rem];
    }
    uint2 wreg[4][8];
#pragma unroll
    for(int cc=0;cc<4;cc++)
#pragma unroll
        for(int ni=0;ni<8;ni++){
            ull v = g_Wpk[w*4096 + 2048 + (4+cc)*256 + ni*32 + lane];
            wreg[cc][ni] = make_uint2((uint32_t)v,(uint32_t)(v>>32));
        }
    for(int i=tid;i<16*ASTR/2;i+=256) ((uint32_t*)A_s)[i]=0;   // h0 = 0

    const uint32_t aBase = smem_u32(A_s) + (uint32_t)(((lane&15)*ASTR + (lane>>4)*8)*2);
    const int ur = tid>>5, um = (tid&31)*4;
    float c_r[4]={0.f,0.f,0.f,0.f};

#pragma unroll 1
    for(int t=0;t<TLEN;t++){
        // stage xp1[t] (coalesced)
        float4 xs[4];
#pragma unroll
        for(int i=0;i<4;i++){
            int fi = tid + i*256;
            xs[i] = *(const float4*)&g_xp1[(((size_t)t)*BATCH + b0 + (fi>>7))*GSZ + (fi&127)*4];
        }
        if(t>0){
            float4 gi=*(float4*)&buf[ur*BUFS+um];
            float4 gf=*(float4*)&buf[ur*BUFS+128+um];
            float4 gg=*(float4*)&buf[ur*BUFS+256+um];
            float4 go=*(float4*)&buf[ur*BUFS+384+um];
            float hv[4], lv[4];
#pragma unroll
            for(int e=0;e<4;e++){
                float iv=sigm(((float*)&gi)[e]);
                float fv=sigm(((float*)&gf)[e]);
                float gv=tanh_f(((float*)&gg)[e]);
                float ov=sigm(((float*)&go)[e]);
                float c=fv*c_r[e]+iv*gv; c_r[e]=c;
                float h=ov*tanh_f(c);
                __nv_bfloat16 hb=__float2bfloat16(h);
                hv[e]=__bfloat162float(hb);
                lv[e]=h-hv[e];
            }
            *(uint2*)&A_s[ur*ASTR+um]     = make_uint2(pkbf(hv[0],hv[1]),pkbf(hv[2],hv[3]));
            *(uint2*)&A_s[(ur+8)*ASTR+um] = make_uint2(pkbf(lv[0],lv[1]),pkbf(lv[2],lv[3]));
        }
#pragma unroll
        for(int i=0;i<4;i++){
            int fi = tid + i*256;
            *(float4*)&buf[(fi>>7)*BUFS + (fi&127)*4] = xs[i];
        }
        __syncthreads();

        float acc[8][4];
#pragma unroll
        for(int ni=0;ni<8;ni++){acc[ni][0]=0;acc[ni][1]=0;acc[ni][2]=0;acc[ni][3]=0;}
#pragma unroll
        for(int c=0;c<8;c++){
            uint32_t a[4];
            LDSM4(a[0],a[1],a[2],a[3], aBase + (uint32_t)(c*32));
            const uint2* whc = (const uint2*)&ws[w*3072 + c*256] + lane;
#pragma unroll
            for(int ni=0;ni<8;ni++){
                uint2 bh = whc[ni*32];
                MMA(acc[ni],a,bh.x,bh.y);
            }
            if(c<4){
                const uint2* wlc = (const uint2*)&ws[w*3072 + (8+c)*256] + lane;
#pragma unroll
                for(int ni=0;ni<8;ni++){
                    uint2 bl = wlc[ni*32];
                    MMA(acc[ni],a,bl.x,bl.y);
                }
            } else {
#pragma unroll
                for(int ni=0;ni<8;ni++)
                    MMA(acc[ni],a,wreg[c-4][ni].x,wreg[c-4][ni].y);
            }
        }
        // gate = xp + D(hi row g) + D(lo row g+8), combined in-thread
#pragma unroll
        for(int ni=0;ni<8;ni++){
            int c0 = w*64 + ni*8 + 2*tq;
            float2 v = *(float2*)&buf[g*BUFS + c0];
            v.x += acc[ni][0] + acc[ni][2];
            v.y += acc[ni][1] + acc[ni][3];
            *(float2*)&buf[g*BUFS + c0] = v;
        }
        __syncthreads();
    }
    {
        float4 gi=*(float4*)&buf[ur*BUFS+um];
        float4 gf=*(float4*)&buf[ur*BUFS+128+um];
        float4 gg=*(float4*)&buf[ur*BUFS+256+um];
        float4 go=*(float4*)&buf[ur*BUFS+384+um];
#pragma unroll
        for(int e=0;e<4;e++){
            float iv=sigm(((float*)&gi)[e]);
            float fv=sigm(((float*)&gf)[e]);
            float gv=tanh_f(((float*)&gg)[e]);
            float ov=sigm(((float*)&go)[e]);
            float c=fv*c_r[e]+iv*gv;
            g_h2[(b0+ur)*HID+um+e]=ov*tanh_f(c);
        }
    }
}

// ---------------- MLP head ----------------
__global__ void head_kernel(const float* __restrict__ W1,const float* __restrict__ b1,
                            const float* __restrict__ W2,const float* __restrict__ b2,
                            const float* __restrict__ W3,const float* __restrict__ b3,
                            float* __restrict__ out){
    __shared__ float hrow[HID]; __shared__ float z1[64]; __shared__ float z2[32];
    int b=blockIdx.x, tid=threadIdx.x;
    hrow[tid]=g_h2[b*HID+tid];
    hrow[tid+64]=g_h2[b*HID+tid+64];
    __syncthreads();
    {
        float s=b1[tid];
        const float* w=&W1[tid*HID];
#pragma unroll 8
        for(int k=0;k<HID;k++) s+=w[k]*hrow[k];
        z1[tid]=fmaxf(s,0.f);
    }
    __syncthreads();
    if(tid<32){
        float s=b2[tid];
        const float* w=&W2[tid*64];
#pragma unroll 8
        for(int k=0;k<64;k++) s+=w[k]*z1[k];
        z2[tid]=fmaxf(s,0.f);
    }
    __syncthreads();
    if(tid<2){
        float s=b3[tid];
        const float* w=&W3[tid*32];
#pragma unroll
        for(int k=0;k<32;k++) s+=w[k]*z2[k];
        out[b*2+tid]=s;
    }
}

// ---------------- launch ----------------
extern "C" void kernel_launch(void* const* d_in, const int* in_sizes, int n_in,
                              void* d_out, int out_size){
    const float* x   =(const float*)d_in[0];
    const float* Wih0=(const float*)d_in[1];
    const float* Whh0=(const float*)d_in[2];
    const float* bih0=(const float*)d_in[3];
    const float* bhh0=(const float*)d_in[4];
    const float* Wih1=(const float*)d_in[5];
    const float* Whh1=(const float*)d_in[6];
    const float* bih1=(const float*)d_in[7];
    const float* bhh1=(const float*)d_in[8];
    const float* W1=(const float*)d_in[9];
    const float* b1=(const float*)d_in[10];
    const float* W2=(const float*)d_in[11];
    const float* b2=(const float*)d_in[12];
    const float* W3=(const float*)d_in[13];
    const float* b3=(const float*)d_in[14];
    float* out=(float*)d_out;

    const int smem0=(SRR*GSZ+KP0*12+8*GSZ)*4;          // 219,904 B
    const int smem1=196608+4352+16512;                  // 217,472 B
    const int smemg=(128*BS2 + 2*64*AS2)*2;             // 167,936 B
    cudaFuncSetAttribute((const void*)lstm0_kernel,cudaFuncAttributeMaxDynamicSharedMemorySize,smem0);
    cudaFuncSetAttribute((const void*)lstm1_tc_kernel,cudaFuncAttributeMaxDynamicSharedMemorySize,smem1);
    cudaFuncSetAttribute((const void*)xp_tc3_kernel,cudaFuncAttributeMaxDynamicSharedMemorySize,smemg);

    int tot=KP0*GSZ+2*GSZ+GSZ*384+32768;
    prep_kernel<<<(tot+255)/256,256>>>(Wih0,Whh0,bih0,bhh0,Wih1,Whh1,bih1,bhh1);
    lstm0_kernel<<<NBLK,256,smem0>>>(x);
    xp_tc3_kernel<<<dim3(128,4),256,smemg>>>();
    lstm1_tc_kernel<<<NBLK,256,smem1>>>();
    head_kernel<<<BATCH,64>>>(W1,b1,W2,b2,W3,b3,out);
}

// round 17
// speedup vs baseline: 1.8060x; 1.1611x over previous
#include <cuda_runtime.h>
#include <cuda_bf16.h>
#include <cstdint>
#include <cstddef>

#define HID 128
#define GSZ 512
#define BATCH 1024
#define TLEN 512
#define DIN 12
#define BT 8
#define NBLK 128
#define MROWS (TLEN*BATCH)
#define AS2 264      // gemm A smem stride (bf16)
#define BS2 392      // gemm B smem stride (bf16)
#define NTILE 64
#define ASTR 136     // scan A_s bf16 row stride
#define BUFS 516     // scan gate/xp fp32 row stride

typedef unsigned long long ull;

extern __shared__ char dynsm[];   // single dynamic-smem declaration

// ---------------- device globals ----------------
__device__ float g_bias1[GSZ];
__device__ __nv_bfloat16 g_h1s[(size_t)MROWS*256];   // h1 [row][hi128|lo128]
__device__ __nv_bfloat16 g_BE[GSZ*384];              // W_ih1 ext [n][384] = wh|wh|wl
__device__ ull g_Wpk[2][32768];                      // packed W_hh frag planes (hi|lo) per layer
__device__ float g_xp0[(size_t)MROWS*GSZ];           // x@Wih0^T + b0,  [t][b][512]
__device__ float g_xp1[(size_t)MROWS*GSZ];           // h1@Wih1^T + b1, [t][b][512]
__device__ float g_h2[BATCH*HID];

// ---------------- helpers ----------------
__device__ __forceinline__ float sigm(float x){return __fdividef(1.0f,1.0f+__expf(-x));}
__device__ __forceinline__ float tanh_f(float x){return __fdividef(2.0f,1.0f+__expf(-2.0f*x))-1.0f;}
__device__ __forceinline__ uint32_t smem_u32(const void* p){
    uint32_t a;
    asm("{ .reg .u64 t; cvta.to.shared.u64 t, %1; cvt.u32.u64 %0, t; }":"=r"(a):"l"(p));
    return a;
}
__device__ __forceinline__ uint32_t pkbf(float a, float b){
    __nv_bfloat16 ha=__float2bfloat16(a), hb=__float2bfloat16(b);
    return (uint32_t)__bfloat16_as_ushort(ha) | ((uint32_t)__bfloat16_as_ushort(hb)<<16);
}

#define MMA(d,a,b0,b1) \
    asm volatile("mma.sync.aligned.m16n8k16.row.col.f32.bf16.bf16.f32 " \
        "{%0,%1,%2,%3},{%4,%5,%6,%7},{%8,%9},{%0,%1,%2,%3};" \
        : "+f"((d)[0]),"+f"((d)[1]),"+f"((d)[2]),"+f"((d)[3]) \
        : "r"((a)[0]),"r"((a)[1]),"r"((a)[2]),"r"((a)[3]),"r"(b0),"r"(b1))

#define LDSM4(r0,r1,r2,r3,addr) \
    asm volatile("ldmatrix.sync.aligned.m8n8.x4.shared.b16 {%0,%1,%2,%3}, [%4];" \
        : "=r"(r0),"=r"(r1),"=r"(r2),"=r"(r3) : "r"(addr))

#define CP16(dst,src) \
    asm volatile("cp.async.cg.shared.global [%0], [%1], 16;"::"r"(dst),"l"(src))
#define CP_COMMIT() asm volatile("cp.async.commit_group;" ::: "memory")
#define CP_WAIT0()  asm volatile("cp.async.wait_group 0;" ::: "memory")

// ---------------- prep: W_ih1 ext planes, bias1, both packed W_hh frag sets --------
__global__ void prep_kernel(const float* __restrict__ Whh0,const float* __restrict__ Whh1,
                            const float* __restrict__ Wih1,
                            const float* __restrict__ bih1,const float* __restrict__ bhh1){
    int i = blockIdx.x*blockDim.x + threadIdx.x;
    const int S0=GSZ, S1=S0+GSZ*384, S2=S1+65536;
    if(i<S0){ g_bias1[i]=bih1[i]+bhh1[i]; }
    else if(i<S1){
        int i2=i-S0; int n=i2/384, kp=i2%384, k=kp&127;
        float w=Wih1[n*HID+k];
        __nv_bfloat16 hi=__float2bfloat16(w);
        g_BE[i2] = (kp<256)? hi : __float2bfloat16(w-__bfloat162float(hi));
    }else if(i<S2){
        // packed W_hh b-frags (canonical m16n8k16 B layout)
        int iu=i-S1;
        int L=iu>>15, u=iu&32767;
        int lane=u&31, ni=(u>>5)&7, c=(u>>8)&7, p=(u>>11)&1, w=(u>>12)&7;
        int g=lane>>2, tq=lane&3;
        int n = w*64 + ni*8 + g;
        int k0 = c*16 + 2*tq;
        const float* W = L ? Whh1 : Whh0;
        float v[4];
#pragma unroll
        for(int e=0;e<4;e++){
            int k = k0 + (e>>1)*8 + (e&1);
            float x = W[n*HID + k];
            __nv_bfloat16 hi = __float2bfloat16(x);
            v[e] = (p==0)? __bfloat162float(hi) : (x - __bfloat162float(hi));
        }
        g_Wpk[L][u] = (ull)pkbf(v[0],v[1]) | ((ull)pkbf(v[2],v[3])<<32);
    }
}

// ---------------- xp0 = x @ Wih0^T + (bih0+bhh0), layout [t][b][512] ----------------
__global__ void __launch_bounds__(256,1) xp0_kernel(const float* __restrict__ x,
        const float* __restrict__ Wih0, const float* __restrict__ bih0,
        const float* __restrict__ bhh0){
    __shared__ float Ws[GSZ*DIN];
    __shared__ float bs[GSZ];
    __shared__ float xs[16*DIN];
    int t = blockIdx.x, bb = blockIdx.y*16, tid = threadIdx.x;
    for(int i=tid;i<GSZ*DIN;i+=256) Ws[i]=Wih0[i];
    for(int i=tid;i<GSZ;i+=256) bs[i]=bih0[i]+bhh0[i];
    if(tid<192){ int r=tid/DIN, d=tid%DIN;
        xs[tid] = x[((size_t)(bb+r)*TLEN + t)*DIN + d]; }
    __syncthreads();
    int r = tid>>4, cl = tid&15;
    const float* xr = &xs[r*DIN];
    float* outp = &g_xp0[(((size_t)t)*BATCH + bb + r)*GSZ];
#pragma unroll 4
    for(int j=0;j<32;j++){
        int col = cl + j*16;
        const float* wj = &Ws[col*DIN];
        float s = bs[col];
#pragma unroll
        for(int d=0;d<DIN;d++) s += xr[d]*wj[d];
        outp[col] = s;
    }
}

// prefetch one 64-row A tile via cp.async (gemm)
__device__ __forceinline__ void prefetchA(size_t mt, __nv_bfloat16* buf, int tid){
    const char* src = (const char*)(g_h1s + mt*64*256);
    uint32_t dbase = smem_u32(buf);
#pragma unroll
    for(int c=0;c<8;c++){
        int chunk = tid + c*256;
        int r = chunk>>5, col16 = chunk&31;
        CP16(dbase + (uint32_t)(r*AS2*2 + col16*16), src + r*512 + col16*16);
    }
    CP_COMMIT();
}

// ---------------- xp1 GEMM (R14-exact: ldmatrix + mma.sync, pipelined) ----------------
__global__ void __launch_bounds__(256,1) xp_tc3_kernel(){
    __nv_bfloat16* Bs = (__nv_bfloat16*)dynsm;
    __nv_bfloat16* A0 = Bs + 128*BS2;
    __nv_bfloat16* A1 = A0 + 64*AS2;
    const int tid=threadIdx.x, wid=tid>>5, lane=tid&31;
    const int g=lane>>2, tq=lane&3;
    const int mset=blockIdx.x, ny=blockIdx.y;
    {
        const float4* bsrc=(const float4*)(g_BE + (size_t)ny*128*384);
        for(int i=tid;i<6144;i+=256){
            int n=i/48, kq=i%48;
            *(float4*)(Bs + n*BS2 + kq*8)=bsrc[i];
        }
    }
    const int mh = (wid&1)*32;
    const int nq = (wid>>1)*32;
    float bx[4], by[4];
#pragma unroll
    for(int ni=0;ni<4;ni++){
        int col=ny*128+nq+ni*8+2*tq;
        bx[ni]=g_bias1[col]; by[ni]=g_bias1[col+1];
    }
    const uint32_t aRowOff = (uint32_t)((mh + (lane&15))*AS2*2 + ((lane>>4)*8)*2);
    const uint32_t bBase = smem_u32(Bs);
    uint32_t bAddr[2];
#pragma unroll
    for(int pr=0;pr<2;pr++)
        bAddr[pr] = bBase + (uint32_t)((nq + pr*16 + (lane&7) + (lane>>4)*8)*BS2*2
                                       + (((lane>>3)&1)*8)*2);
    prefetchA((size_t)mset, A0, tid);
    __syncthreads();
#pragma unroll 1
    for(int i=0;i<NTILE;i++){
        __nv_bfloat16* Ac = (i&1)? A1 : A0;
        CP_WAIT0();
        __syncthreads();
        if(i+1<NTILE)
            prefetchA((size_t)mset + 128*(size_t)(i+1), (i&1)? A0 : A1, tid);
        const uint32_t aBase = smem_u32(Ac) + aRowOff;
        float acc[2][4][4];
#pragma unroll
        for(int mi=0;mi<2;mi++)
#pragma unroll
            for(int ni=0;ni<4;ni++)
#pragma unroll
                for(int q=0;q<4;q++) acc[mi][ni][q]=0.f;
#pragma unroll 4
        for(int kc=0;kc<24;kc++){
            int ks=(kc<8)?kc*16:(kc<16)?(128+(kc-8)*16):((kc-16)*16);
            int kb=kc*16;
            uint32_t a[2][4];
#pragma unroll
            for(int mi=0;mi<2;mi++)
                LDSM4(a[mi][0],a[mi][1],a[mi][2],a[mi][3],
                      aBase + (uint32_t)(mi*16*AS2*2 + ks*2));
            uint32_t b[2][4];
#pragma unroll
            for(int pr=0;pr<2;pr++)
                LDSM4(b[pr][0],b[pr][1],b[pr][2],b[pr][3],
                      bAddr[pr] + (uint32_t)(kb*2));
#pragma unroll
            for(int mi=0;mi<2;mi++){
                MMA(acc[mi][0],a[mi],b[0][0],b[0][1]);
                MMA(acc[mi][1],a[mi],b[0][2],b[0][3]);
                MMA(acc[mi][2],a[mi],b[1][0],b[1][1]);
                MMA(acc[mi][3],a[mi],b[1][2],b[1][3]);
            }
        }
        {
            int colb=ny*128+nq;
#pragma unroll
            for(int mi=0;mi<2;mi++){
                size_t r0=((size_t)mset + 128*(size_t)i)*64 + mh + mi*16 + g;
#pragma unroll
                for(int ni=0;ni<4;ni++){
                    int col=colb+ni*8+2*tq;
                    *(float2*)&g_xp1[r0*GSZ+col]     = make_float2(acc[mi][ni][0]+bx[ni], acc[mi][ni][1]+by[ni]);
                    *(float2*)&g_xp1[(r0+8)*GSZ+col] = make_float2(acc[mi][ni][2]+bx[ni], acc[mi][ni][3]+by[ni]);
                }
            }
        }
        __syncthreads();
    }
}

// ---------------- tensor-core LSTM scan (both layers; R16-validated structure) ------
// 128 blocks x 256 threads; 8 batch rows. A_s = [h_hi(8); h_lo(8)] rows, M=16 MMA.
// Per step: 8 k-chunks x 8 n-tiles x (hi+lo planes) = 128 MMA/warp. A via ldmatrix.x4.
// LAYER 0 additionally writes the h1 hi/lo planes consumed by the xp1 GEMM.
template <int LAYER>
__global__ void __launch_bounds__(256,1) lstm_tc_kernel(){
    ull*  ws  = (ull*)dynsm;                               // 196,608 B
    __nv_bfloat16* A_s = (__nv_bfloat16*)(dynsm + 196608); // 4,352 B
    float* buf = (float*)(dynsm + 196608 + 4352);          // 16,512 B

    const float* __restrict__ xp = LAYER ? g_xp1 : g_xp0;
    const ull* __restrict__ wpk = g_Wpk[LAYER];
    const int tid = threadIdx.x;
    const int w = tid>>5, lane = tid&31, g = lane>>2, tq = lane&3;
    const int b0 = blockIdx.x*BT;

    for(int i=lane;i<3072;i+=32){
        int s=i>>8, rem=i&255;
        ws[w*3072+i] = wpk[w*4096 + (s<8 ? s*256 : 2048+(s-8)*256) + rem];
    }
    uint2 wreg[4][8];
#pragma unroll
    for(int cc=0;cc<4;cc++)
#pragma unroll
        for(int ni=0;ni<8;ni++){
            ull v = wpk[w*4096 + 2048 + (4+cc)*256 + ni*32 + lane];
            wreg[cc][ni] = make_uint2((uint32_t)v,(uint32_t)(v>>32));
        }
    for(int i=tid;i<16*ASTR/2;i+=256) ((uint32_t*)A_s)[i]=0;   // h0 = 0

    const uint32_t aBase = smem_u32(A_s) + (uint32_t)(((lane&15)*ASTR + (lane>>4)*8)*2);
    const int ur = tid>>5, um = (tid&31)*4;
    float c_r[4]={0.f,0.f,0.f,0.f};

#pragma unroll 1
    for(int t=0;t<TLEN;t++){
        // stage xp[t] (coalesced)
        float4 xs[4];
#pragma unroll
        for(int i=0;i<4;i++){
            int fi = tid + i*256;
            xs[i] = *(const float4*)&xp[(((size_t)t)*BATCH + b0 + (fi>>7))*GSZ + (fi&127)*4];
        }
        if(t>0){
            float4 gi=*(float4*)&buf[ur*BUFS+um];
            float4 gf=*(float4*)&buf[ur*BUFS+128+um];
            float4 gg=*(float4*)&buf[ur*BUFS+256+um];
            float4 go=*(float4*)&buf[ur*BUFS+384+um];
            float hv[4], lv[4];
#pragma unroll
            for(int e=0;e<4;e++){
                float iv=sigm(((float*)&gi)[e]);
                float fv=sigm(((float*)&gf)[e]);
                float gv=tanh_f(((float*)&gg)[e]);
                float ov=sigm(((float*)&go)[e]);
                float c=fv*c_r[e]+iv*gv; c_r[e]=c;
                float h=ov*tanh_f(c);
                __nv_bfloat16 hb=__float2bfloat16(h);
                hv[e]=__bfloat162float(hb);
                lv[e]=h-hv[e];
            }
            uint2 ph = make_uint2(pkbf(hv[0],hv[1]),pkbf(hv[2],hv[3]));
            uint2 pl = make_uint2(pkbf(lv[0],lv[1]),pkbf(lv[2],lv[3]));
            *(uint2*)&A_s[ur*ASTR+um]     = ph;
            *(uint2*)&A_s[(ur+8)*ASTR+um] = pl;
            if(LAYER==0){
                size_t row=((size_t)(t-1))*BATCH+b0+ur;
                *(uint2*)&g_h1s[row*256+um]     = ph;
                *(uint2*)&g_h1s[row*256+128+um] = pl;
            }
        }
#pragma unroll
        for(int i=0;i<4;i++){
            int fi = tid + i*256;
            *(float4*)&buf[(fi>>7)*BUFS + (fi&127)*4] = xs[i];
        }
        __syncthreads();

        float acc[8][4];
#pragma unroll
        for(int ni=0;ni<8;ni++){acc[ni][0]=0;acc[ni][1]=0;acc[ni][2]=0;acc[ni][3]=0;}
#pragma unroll
        for(int c=0;c<8;c++){
            uint32_t a[4];
            LDSM4(a[0],a[1],a[2],a[3], aBase + (uint32_t)(c*32));
            const uint2* whc = (const uint2*)&ws[w*3072 + c*256] + lane;
#pragma unroll
            for(int ni=0;ni<8;ni++){
                uint2 bh = whc[ni*32];
                MMA(acc[ni],a,bh.x,bh.y);
            }
            if(c<4){
                const uint2* wlc = (const uint2*)&ws[w*3072 + (8+c)*256] + lane;
#pragma unroll
                for(int ni=0;ni<8;ni++){
                    uint2 bl = wlc[ni*32];
                    MMA(acc[ni],a,bl.x,bl.y);
                }
            } else {
#pragma unroll
                for(int ni=0;ni<8;ni++)
                    MMA(acc[ni],a,wreg[c-4][ni].x,wreg[c-4][ni].y);
            }
        }
        // gate = xp + D(hi row g) + D(lo row g+8), combined in-thread
#pragma unroll
        for(int ni=0;ni<8;ni++){
            int c0 = w*64 + ni*8 + 2*tq;
            float2 v = *(float2*)&buf[g*BUFS + c0];
            v.x += acc[ni][0] + acc[ni][2];
            v.y += acc[ni][1] + acc[ni][3];
            *(float2*)&buf[g*BUFS + c0] = v;
        }
        __syncthreads();
    }
    // final update (t = T-1)
    {
        float4 gi=*(float4*)&buf[ur*BUFS+um];
        float4 gf=*(float4*)&buf[ur*BUFS+128+um];
        float4 gg=*(float4*)&buf[ur*BUFS+256+um];
        float4 go=*(float4*)&buf[ur*BUFS+384+um];
        float hv[4], lv[4];
#pragma unroll
        for(int e=0;e<4;e++){
            float iv=sigm(((float*)&gi)[e]);
            float fv=sigm(((float*)&gf)[e]);
            float gv=tanh_f(((float*)&gg)[e]);
            float ov=sigm(((float*)&go)[e]);
            float c=fv*c_r[e]+iv*gv;
            float h=ov*tanh_f(c);
            if(LAYER==1) g_h2[(b0+ur)*HID+um+e]=h;
            __nv_bfloat16 hb=__float2bfloat16(h);
            hv[e]=__bfloat162float(hb);
            lv[e]=h-hv[e];
        }
        if(LAYER==0){
            size_t row=((size_t)(TLEN-1))*BATCH+b0+ur;
            *(uint2*)&g_h1s[row*256+um]     = make_uint2(pkbf(hv[0],hv[1]),pkbf(hv[2],hv[3]));
            *(uint2*)&g_h1s[row*256+128+um] = make_uint2(pkbf(lv[0],lv[1]),pkbf(lv[2],lv[3]));
        }
    }
}

// ---------------- MLP head ----------------
__global__ void head_kernel(const float* __restrict__ W1,const float* __restrict__ b1,
                            const float* __restrict__ W2,const float* __restrict__ b2,
                            const float* __restrict__ W3,const float* __restrict__ b3,
                            float* __restrict__ out){
    __shared__ float hrow[HID]; __shared__ float z1[64]; __shared__ float z2[32];
    int b=blockIdx.x, tid=threadIdx.x;
    hrow[tid]=g_h2[b*HID+tid];
    hrow[tid+64]=g_h2[b*HID+tid+64];
    __syncthreads();
    {
        float s=b1[tid];
        const float* w=&W1[tid*HID];
#pragma unroll 8
        for(int k=0;k<HID;k++) s+=w[k]*hrow[k];
        z1[tid]=fmaxf(s,0.f);
    }
    __syncthreads();
    if(tid<32){
        float s=b2[tid];
        const float* w=&W2[tid*64];
#pragma unroll 8
        for(int k=0;k<64;k++) s+=w[k]*z1[k];
        z2[tid]=fmaxf(s,0.f);
    }
    __syncthreads();
    if(tid<2){
        float s=b3[tid];
        const float* w=&W3[tid*32];
#pragma unroll
        for(int k=0;k<32;k++) s+=w[k]*z2[k];
        out[b*2+tid]=s;
    }
}

// ---------------- launch ----------------
extern "C" void kernel_launch(void* const* d_in, const int* in_sizes, int n_in,
                              void* d_out, int out_size){
    const float* x   =(const float*)d_in[0];
    const float* Wih0=(const float*)d_in[1];
    const float* Whh0=(const float*)d_in[2];
    const float* bih0=(const float*)d_in[3];
    const float* bhh0=(const float*)d_in[4];
    const float* Wih1=(const float*)d_in[5];
    const float* Whh1=(const float*)d_in[6];
    const float* bih1=(const float*)d_in[7];
    const float* bhh1=(const float*)d_in[8];
    const float* W1=(const float*)d_in[9];
    const float* b1=(const float*)d_in[10];
    const float* W2=(const float*)d_in[11];
    const float* b2=(const float*)d_in[12];
    const float* W3=(const float*)d_in[13];
    const float* b3=(const float*)d_in[14];
    float* out=(float*)d_out;

    const int smems=196608+4352+16512;                  // 217,472 B
    const int smemg=(128*BS2 + 2*64*AS2)*2;             // 167,936 B
    cudaFuncSetAttribute((const void*)lstm_tc_kernel<0>,cudaFuncAttributeMaxDynamicSharedMemorySize,smems);
    cudaFuncSetAttribute((const void*)lstm_tc_kernel<1>,cudaFuncAttributeMaxDynamicSharedMemorySize,smems);
    cudaFuncSetAttribute((const void*)xp_tc3_kernel,cudaFuncAttributeMaxDynamicSharedMemorySize,smemg);

    int tot = GSZ + GSZ*384 + 65536;
    prep_kernel<<<(tot+255)/256,256>>>(Whh0,Whh1,Wih1,bih1,bhh1);
    xp0_kernel<<<dim3(TLEN,BATCH/16),256>>>(x,Wih0,bih0,bhh0);
    lstm_tc_kernel<0><<<NBLK,256,smems>>>();
    xp_tc3_kernel<<<dim3(128,4),256,smemg>>>();
    lstm_tc_kernel<1><<<NBLK,256,smems>>>();
    head_kernel<<<BATCH,64>>>(W1,b1,W2,b2,W3,b3,out);
}